// round 5
// baseline (speedup 1.0000x reference)
#include <cuda_runtime.h>
#include <cuda_bf16.h>
#include <math.h>
#include <stdint.h>

#define B_    8192
#define DIN_  1024
#define H_    2048
#define DOUT_ 1024
#define E_    8

// ---------------------------------------------------------------------------
// Scratch (allocation-free __device__ globals)
// ---------------------------------------------------------------------------
#define WPE 16777216ull  // weight elements per expert (5 layers, transposed [N,K])
#define NPE 9216         // n-scale entries per expert (2048*4 + 1024)
__device__ int8_t g_Wq1[WPE * E_];
__device__ int8_t g_Wq2[WPE * E_];
__device__ float  g_wamax[(size_t)NPE * E_];
__device__ int8_t g_x1[(size_t)B_ * DIN_];
__device__ int8_t g_x2[(size_t)B_ * DIN_];
__device__ float  g_sAx[B_];
__device__ int8_t g_A1[(size_t)B_ * H_];
__device__ int8_t g_A2[(size_t)B_ * H_];
__device__ float  g_sA[B_];
__device__ float  g_C[(size_t)B_ * H_];
__device__ float  g_gate[(size_t)B_ * E_];

// ---------------------------------------------------------------------------
// PTX helpers
// ---------------------------------------------------------------------------
__device__ __forceinline__ uint32_t smem_to_u32(const void* smem_ptr) {
    uint32_t addr;
    asm("{ .reg .u64 tmp; cvta.to.shared.u64 tmp, %1; cvt.u32.u64 %0, tmp; }"
        : "=r"(addr) : "l"(smem_ptr));
    return addr;
}

#define CP_ASYNC16(dst, src) \
    asm volatile("cp.async.cg.shared.global [%0], [%1], 16;" \
                 :: "r"((uint32_t)(dst)), "l"(src) : "memory")

__device__ __forceinline__ void ldsm_x4(uint32_t* r, uint32_t addr) {
    asm volatile("ldmatrix.sync.aligned.m8n8.x4.shared.b16 {%0,%1,%2,%3}, [%4];"
                 : "=r"(r[0]), "=r"(r[1]), "=r"(r[2]), "=r"(r[3]) : "r"(addr));
}

__device__ __forceinline__ void mma_s8(int* c, const uint32_t* a, const uint32_t* b) {
    asm volatile(
        "mma.sync.aligned.m16n8k32.row.col.s32.s8.s8.s32 "
        "{%0,%1,%2,%3}, {%4,%5,%6,%7}, {%8,%9}, {%0,%1,%2,%3};"
        : "+r"(c[0]), "+r"(c[1]), "+r"(c[2]), "+r"(c[3])
        : "r"(a[0]), "r"(a[1]), "r"(a[2]), "r"(a[3]), "r"(b[0]), "r"(b[1]));
}

// ---------------------------------------------------------------------------
// Gate: softmax(x @ Wg + bg) per row. One warp/row.
// ---------------------------------------------------------------------------
__global__ void gate_kernel(const float* __restrict__ x,
                            const float* __restrict__ Wg,
                            const float* __restrict__ bg) {
    int gwarp = (blockIdx.x * blockDim.x + threadIdx.x) >> 5;
    int lane  = threadIdx.x & 31;
    if (gwarp >= B_) return;
    const float* xr = x + (size_t)gwarp * DIN_;
    float acc[E_];
#pragma unroll
    for (int e = 0; e < E_; e++) acc[e] = 0.f;
    for (int i = lane; i < DIN_; i += 32) {
        float xv = xr[i];
        const float4* w4 = reinterpret_cast<const float4*>(Wg + (size_t)i * E_);
        float4 w0 = w4[0], w1 = w4[1];
        acc[0] += xv * w0.x; acc[1] += xv * w0.y;
        acc[2] += xv * w0.z; acc[3] += xv * w0.w;
        acc[4] += xv * w1.x; acc[5] += xv * w1.y;
        acc[6] += xv * w1.z; acc[7] += xv * w1.w;
    }
#pragma unroll
    for (int e = 0; e < E_; e++) {
#pragma unroll
        for (int o = 16; o > 0; o >>= 1)
            acc[e] += __shfl_xor_sync(0xffffffffu, acc[e], o);
    }
    if (lane == 0) {
        float mx = -1e30f;
#pragma unroll
        for (int e = 0; e < E_; e++) { acc[e] += bg[e]; mx = fmaxf(mx, acc[e]); }
        float s = 0.f;
#pragma unroll
        for (int e = 0; e < E_; e++) { acc[e] = expf(acc[e] - mx); s += acc[e]; }
        float inv = 1.f / s;
#pragma unroll
        for (int e = 0; e < E_; e++) g_gate[(size_t)gwarp * E_ + e] = acc[e] * inv;
    }
}

// ---------------------------------------------------------------------------
// Per-output-channel weight amax: W [K,N] -> amax[n] (atomicMax on +floats).
// ---------------------------------------------------------------------------
__global__ void wamax_kernel(const float* __restrict__ W, float* __restrict__ amax,
                             int K, int N) {
    int n = blockIdx.x * 256 + threadIdx.x;
    int kchunk = K >> 3;
    int k0 = blockIdx.y * kchunk;
    float m = 0.f;
    for (int k = k0; k < k0 + kchunk; k++)
        m = fmaxf(m, fabsf(W[(size_t)k * N + n]));
    atomicMax(reinterpret_cast<int*>(&amax[n]), __float_as_int(m));
}

// ---------------------------------------------------------------------------
// Weight quantize+transpose: W [K,N] fp32 -> Q1/Q2 [N,K] int8 (two-level).
// ---------------------------------------------------------------------------
__global__ void wconv_q(const float* __restrict__ W, const float* __restrict__ amax,
                        int8_t* __restrict__ Q1, int8_t* __restrict__ Q2,
                        int K, int N) {
    __shared__ float t[128][33];
    const int n0 = blockIdx.x * 32, k0 = blockIdx.y * 128;
    const int tx = threadIdx.x, ty = threadIdx.y;  // 32x8
#pragma unroll
    for (int r = 0; r < 16; r++) {
        int k = ty + r * 8;
        t[k][tx] = W[(size_t)(k0 + k) * N + n0 + tx];
    }
    __syncthreads();
#pragma unroll
    for (int r = 0; r < 4; r++) {
        int n = ty + r * 8;
        float am = amax[n0 + n];
        float inv = (am > 0.f) ? 127.f / am : 0.f;
        char q1[4], q2[4];
#pragma unroll
        for (int c = 0; c < 4; c++) {
            float q = t[tx * 4 + c][n] * inv;
            float q1f = rintf(q);
            q1[c] = (char)(int)q1f;
            q2[c] = (char)__float2int_rn((q - q1f) * 254.f);
        }
        size_t o = (size_t)(n0 + n) * K + k0 + tx * 4;
        *reinterpret_cast<char4*>(&Q1[o]) = make_char4(q1[0], q1[1], q1[2], q1[3]);
        *reinterpret_cast<char4*>(&Q2[o]) = make_char4(q2[0], q2[1], q2[2], q2[3]);
    }
}

// ---------------------------------------------------------------------------
// Block reductions (256 threads)
// ---------------------------------------------------------------------------
__device__ __forceinline__ float block_reduce_sum(float v, float* sred) {
    __syncthreads();
#pragma unroll
    for (int o = 16; o > 0; o >>= 1) v += __shfl_xor_sync(0xffffffffu, v, o);
    const int w = threadIdx.x >> 5;
    if ((threadIdx.x & 31) == 0) sred[w] = v;
    __syncthreads();
    if (threadIdx.x < 32) {
        float r = (threadIdx.x < 8) ? sred[threadIdx.x] : 0.f;
#pragma unroll
        for (int o = 4; o > 0; o >>= 1) r += __shfl_xor_sync(0xffffffffu, r, o);
        if (threadIdx.x == 0) sred[0] = r;
    }
    __syncthreads();
    return sred[0];
}

__device__ __forceinline__ float block_reduce_max(float v, float* sred) {
    __syncthreads();
#pragma unroll
    for (int o = 16; o > 0; o >>= 1) v = fmaxf(v, __shfl_xor_sync(0xffffffffu, v, o));
    const int w = threadIdx.x >> 5;
    if ((threadIdx.x & 31) == 0) sred[w] = v;
    __syncthreads();
    if (threadIdx.x < 32) {
        float r = (threadIdx.x < 8) ? sred[threadIdx.x] : 0.f;
#pragma unroll
        for (int o = 4; o > 0; o >>= 1) r = fmaxf(r, __shfl_xor_sync(0xffffffffu, r, o));
        if (threadIdx.x == 0) sred[0] = r;
    }
    __syncthreads();
    return sred[0];
}

// ---------------------------------------------------------------------------
// x quantize: per-row amax + two-level int8. One block per row (1024 elems).
// ---------------------------------------------------------------------------
__global__ void xconv_q(const float* __restrict__ x, int8_t* __restrict__ X1,
                        int8_t* __restrict__ X2, float* __restrict__ sA) {
    __shared__ float sred[32];
    const int row = blockIdx.x, t = threadIdx.x;
    float4 v = reinterpret_cast<const float4*>(x + (size_t)row * DIN_)[t];
    float vals[4] = {v.x, v.y, v.z, v.w};
    float am = 0.f;
#pragma unroll
    for (int i = 0; i < 4; i++) am = fmaxf(am, fabsf(vals[i]));
    am = block_reduce_max(am, sred);
    if (t == 0) sA[row] = am * (1.f / 127.f);
    float inv = (am > 0.f) ? 127.f / am : 0.f;
    char q1[4], q2[4];
#pragma unroll
    for (int i = 0; i < 4; i++) {
        float q = vals[i] * inv;
        float q1f = rintf(q);
        q1[i] = (char)(int)q1f;
        q2[i] = (char)__float2int_rn((q - q1f) * 254.f);
    }
    size_t o = (size_t)row * DIN_ + t * 4;
    *reinterpret_cast<char4*>(&X1[o]) = make_char4(q1[0], q1[1], q1[2], q1[3]);
    *reinterpret_cast<char4*>(&X2[o]) = make_char4(q2[0], q2[1], q2[2], q2[3]);
}

// ---------------------------------------------------------------------------
// mish + LayerNorm + two-level int8 quantize. One block per row of 2048.
// ---------------------------------------------------------------------------
__global__ void mish_ln_q(const float* __restrict__ in, int8_t* __restrict__ A1,
                          int8_t* __restrict__ A2, float* __restrict__ sA) {
    __shared__ float sred[32];
    const int t = threadIdx.x;
    const size_t rowoff = (size_t)blockIdx.x * H_;
    const float4* p = reinterpret_cast<const float4*>(in + rowoff);
    float4 v0 = p[t], v1 = p[t + 256];
    float vals[8] = {v0.x, v0.y, v0.z, v0.w, v1.x, v1.y, v1.z, v1.w};
    float s = 0.f;
#pragma unroll
    for (int i = 0; i < 8; i++) {
        float h = vals[i];
        float sp = (h > 20.f) ? h : log1pf(expf(h));
        float m = h * tanhf(sp);
        vals[i] = m;
        s += m;
    }
    s = block_reduce_sum(s, sred);
    const float mu = s * (1.f / H_);
    float q = 0.f;
#pragma unroll
    for (int i = 0; i < 8; i++) { float d = vals[i] - mu; q += d * d; }
    q = block_reduce_sum(q, sred);
    const float inv = rsqrtf(q * (1.f / H_) + 1e-5f);
    float am = 0.f;
#pragma unroll
    for (int i = 0; i < 8; i++) {
        vals[i] = (vals[i] - mu) * inv;
        am = fmaxf(am, fabsf(vals[i]));
    }
    am = block_reduce_max(am, sred);
    if (t == 0) sA[blockIdx.x] = am * (1.f / 127.f);
    float qinv = (am > 0.f) ? 127.f / am : 0.f;
    char q1[8], q2[8];
#pragma unroll
    for (int i = 0; i < 8; i++) {
        float qq = vals[i] * qinv;
        float q1f = rintf(qq);
        q1[i] = (char)(int)q1f;
        q2[i] = (char)__float2int_rn((qq - q1f) * 254.f);
    }
    *reinterpret_cast<char4*>(&A1[rowoff + t * 4])        = make_char4(q1[0], q1[1], q1[2], q1[3]);
    *reinterpret_cast<char4*>(&A1[rowoff + 1024 + t * 4]) = make_char4(q1[4], q1[5], q1[6], q1[7]);
    *reinterpret_cast<char4*>(&A2[rowoff + t * 4])        = make_char4(q2[0], q2[1], q2[2], q2[3]);
    *reinterpret_cast<char4*>(&A2[rowoff + 1024 + t * 4]) = make_char4(q2[4], q2[5], q2[6], q2[7]);
}

// ---------------------------------------------------------------------------
// IMMA two-level int8 GEMM. CTA 128x128, warp 64x32, K-chunk 64 (int8),
// 4-stage cp.async. D = sA*sB*(A1B1 + (A1B2 + A2B1)/254). int32 accum (exact).
// Byte layout identical to the proven bf16 kernel (32B per k-tile slice).
// ---------------------------------------------------------------------------
#define STRIDE_B 80                      // padded row stride in bytes
#define MAT_BYTES (128 * STRIDE_B)       // 10240
#define STAGE_BYTES (4 * MAT_BYTES)      // 40960
#define NSTAGE 4
#define GEMM_SMEM (NSTAGE * STAGE_BYTES) // 163840

__device__ __forceinline__ void copy_stage(uint32_t st, int tid, int kc, int K,
                                           const int8_t* a1, const int8_t* a2,
                                           const int8_t* b1, const int8_t* b2) {
    const int8_t* srcs[4] = {a1, a2, b1, b2};
#pragma unroll
    for (int m = 0; m < 4; m++) {
#pragma unroll
        for (int q = 0; q < 2; q++) {
            int c = tid * 2 + q;          // 0..511
            int row = c >> 2;             // 0..127
            int kch = c & 3;              // 16B chunk within the 64B row
            uint32_t dst = st + m * MAT_BYTES + row * STRIDE_B + kch * 16;
            const int8_t* src = srcs[m] + (size_t)row * K + kc * 64 + kch * 16;
            CP_ASYNC16(dst, src);
        }
    }
    asm volatile("cp.async.commit_group;" ::: "memory");
}

template <int MODE>
__global__ __launch_bounds__(256, 1)
void tc_gemm(const int8_t* __restrict__ A1g, const int8_t* __restrict__ A2g,
             const int8_t* __restrict__ B1g, const int8_t* __restrict__ B2g,
             const float* __restrict__ sA, const float* __restrict__ wamax,
             const float* __restrict__ bias, float* __restrict__ C,
             int N, int K, int expert, int isFirst) {
    extern __shared__ __align__(16) char dynsmem[];
    const uint32_t sbase = smem_to_u32(dynsmem);

    const int tid = threadIdx.x;
    const int wid = tid >> 5;
    const int lane = tid & 31;
    const int wm = wid & 1;       // 2 warps in M
    const int wn = wid >> 1;      // 4 warps in N
    const int KT = K >> 6;        // 64 int8 per chunk

    const int8_t* a1 = A1g + (size_t)(blockIdx.y * 128) * K;
    const int8_t* a2 = A2g + (size_t)(blockIdx.y * 128) * K;
    const int8_t* b1 = B1g + (size_t)(blockIdx.x * 128) * K;
    const int8_t* b2 = B2g + (size_t)(blockIdx.x * 128) * K;

    int acc1[4][4][4], accX[4][4][4];
#pragma unroll
    for (int i = 0; i < 4; i++)
#pragma unroll
        for (int j = 0; j < 4; j++)
#pragma unroll
            for (int q = 0; q < 4; q++) { acc1[i][j][q] = 0; accX[i][j][q] = 0; }

    copy_stage(sbase + 0 * STAGE_BYTES, tid, 0, K, a1, a2, b1, b2);
    copy_stage(sbase + 1 * STAGE_BYTES, tid, 1, K, a1, a2, b1, b2);
    copy_stage(sbase + 2 * STAGE_BYTES, tid, 2, K, a1, a2, b1, b2);

    // Byte-offset ldmatrix addressing (identical to proven bf16 layout)
    const uint32_t a_row = wm * 64 + (lane & 15);
    const uint32_t a_koff = (lane >> 4) * 16;
    const uint32_t b_row = wn * 32 + (lane >> 4) * 8 + (lane & 7);
    const uint32_t b_koff = ((lane >> 3) & 1) * 16;

    for (int kc = 0; kc < KT; kc++) {
        if (kc + 2 < KT)      asm volatile("cp.async.wait_group 2;" ::: "memory");
        else if (kc + 1 < KT) asm volatile("cp.async.wait_group 1;" ::: "memory");
        else                  asm volatile("cp.async.wait_group 0;" ::: "memory");
        __syncthreads();
        if (kc + 3 < KT)
            copy_stage(sbase + ((kc + 3) & 3) * STAGE_BYTES, tid, kc + 3, K, a1, a2, b1, b2);

        const uint32_t st = sbase + (kc & 3) * STAGE_BYTES;
        const uint32_t A1_b = st;
        const uint32_t A2_b = st + MAT_BYTES;
        const uint32_t B1_b = st + 2 * MAT_BYTES;
        const uint32_t B2_b = st + 3 * MAT_BYTES;

#pragma unroll
        for (int h = 0; h < 2; h++) {     // two k32 halves of the 64B chunk
            const uint32_t kbyte = h * 32;
            uint32_t fa1[16], fa2[16], fb1[8], fb2[8];
#pragma unroll
            for (int i = 0; i < 4; i++) {
                uint32_t off = (a_row + i * 16) * STRIDE_B + kbyte + a_koff;
                ldsm_x4(&fa1[i * 4], A1_b + off);
                ldsm_x4(&fa2[i * 4], A2_b + off);
            }
#pragma unroll
            for (int p = 0; p < 2; p++) {
                uint32_t off = (b_row + p * 16) * STRIDE_B + kbyte + b_koff;
                ldsm_x4(&fb1[p * 4], B1_b + off);
                ldsm_x4(&fb2[p * 4], B2_b + off);
            }
            // 48 MMAs grouped by pass; 16 independent acc tiles per pass
#pragma unroll
            for (int i = 0; i < 4; i++)
#pragma unroll
                for (int j = 0; j < 4; j++)
                    mma_s8(acc1[i][j], &fa1[i * 4], &fb1[(j >> 1) * 4 + (j & 1) * 2]);
#pragma unroll
            for (int i = 0; i < 4; i++)
#pragma unroll
                for (int j = 0; j < 4; j++)
                    mma_s8(accX[i][j], &fa1[i * 4], &fb2[(j >> 1) * 4 + (j & 1) * 2]);
#pragma unroll
            for (int i = 0; i < 4; i++)
#pragma unroll
                for (int j = 0; j < 4; j++)
                    mma_s8(accX[i][j], &fa2[i * 4], &fb1[(j >> 1) * 4 + (j & 1) * 2]);
        }
    }

    // Epilogue: dequant + bias (+ gate accumulate for MODE 1)
    const int r0 = blockIdx.y * 128 + wm * 64 + (lane >> 2);
    const int cbase = blockIdx.x * 128 + wn * 32 + (lane & 3) * 2;
    const float inv127 = 1.f / 127.f;
    const float inv254 = 1.f / 254.f;
#pragma unroll
    for (int i = 0; i < 4; i++) {
        const int rowA = r0 + i * 16;
        const int rowB = rowA + 8;
        const float saA = sA[rowA];
        const float saB = sA[rowB];
        float gA = 0.f, gB = 0.f;
        if (MODE == 1) {
            gA = g_gate[(size_t)rowA * E_ + expert];
            gB = g_gate[(size_t)rowB * E_ + expert];
        }
#pragma unroll
        for (int j = 0; j < 4; j++) {
            const int col = cbase + j * 8;
            const float w0 = wamax[col] * inv127;
            const float w1 = wamax[col + 1] * inv127;
            const float b0 = bias[col], b1v = bias[col + 1];
            float d0 = (float)acc1[i][j][0] + (float)accX[i][j][0] * inv254;
            float d1 = (float)acc1[i][j][1] + (float)accX[i][j][1] * inv254;
            float d2 = (float)acc1[i][j][2] + (float)accX[i][j][2] * inv254;
            float d3 = (float)acc1[i][j][3] + (float)accX[i][j][3] * inv254;
            float vA0 = saA * w0 * d0 + b0, vA1 = saA * w1 * d1 + b1v;
            float vB0 = saB * w0 * d2 + b0, vB1 = saB * w1 * d3 + b1v;
            float* pA = C + (size_t)rowA * N + col;
            float* pB = C + (size_t)rowB * N + col;
            if (MODE == 0) {
                *reinterpret_cast<float2*>(pA) = make_float2(vA0, vA1);
                *reinterpret_cast<float2*>(pB) = make_float2(vB0, vB1);
            } else {
                float2 oA = isFirst ? make_float2(0.f, 0.f)
                                    : *reinterpret_cast<const float2*>(pA);
                float2 oB = isFirst ? make_float2(0.f, 0.f)
                                    : *reinterpret_cast<const float2*>(pB);
                oA.x += gA * vA0; oA.y += gA * vA1;
                oB.x += gB * vB0; oB.y += gB * vB1;
                *reinterpret_cast<float2*>(pA) = oA;
                *reinterpret_cast<float2*>(pB) = oB;
            }
        }
    }
}

// ---------------------------------------------------------------------------
// Launch
// ---------------------------------------------------------------------------
extern "C" void kernel_launch(void* const* d_in, const int* in_sizes, int n_in,
                              void* d_out, int out_size) {
    const float* x  = (const float*)d_in[0];
    const float* Wg = (const float*)d_in[1];
    const float* bg = (const float*)d_in[2];
    const float* W1 = (const float*)d_in[3];
    const float* b1 = (const float*)d_in[4];
    const float* W2 = (const float*)d_in[5];
    const float* b2 = (const float*)d_in[6];
    const float* W3 = (const float*)d_in[7];
    const float* b3 = (const float*)d_in[8];
    const float* W4 = (const float*)d_in[9];
    const float* b4 = (const float*)d_in[10];
    const float* W5 = (const float*)d_in[11];
    const float* b5 = (const float*)d_in[12];
    float* out = (float*)d_out;

    void *pWq1, *pWq2, *pwam, *px1, *px2, *psx, *pA1, *pA2, *psa, *pC;
    cudaGetSymbolAddress(&pWq1, g_Wq1);
    cudaGetSymbolAddress(&pWq2, g_Wq2);
    cudaGetSymbolAddress(&pwam, g_wamax);
    cudaGetSymbolAddress(&px1, g_x1);
    cudaGetSymbolAddress(&px2, g_x2);
    cudaGetSymbolAddress(&psx, g_sAx);
    cudaGetSymbolAddress(&pA1, g_A1);
    cudaGetSymbolAddress(&pA2, g_A2);
    cudaGetSymbolAddress(&psa, g_sA);
    cudaGetSymbolAddress(&pC, g_C);
    int8_t* Wq1 = (int8_t*)pWq1;
    int8_t* Wq2 = (int8_t*)pWq2;
    float* wam = (float*)pwam;
    int8_t* X1 = (int8_t*)px1;
    int8_t* X2 = (int8_t*)px2;
    float* sAx = (float*)psx;
    int8_t* A1 = (int8_t*)pA1;
    int8_t* A2 = (int8_t*)pA2;
    float* sA = (float*)psa;
    float* Cbuf = (float*)pC;

    cudaFuncSetAttribute(tc_gemm<0>, cudaFuncAttributeMaxDynamicSharedMemorySize, GEMM_SMEM);
    cudaFuncSetAttribute(tc_gemm<1>, cudaFuncAttributeMaxDynamicSharedMemorySize, GEMM_SMEM);

    gate_kernel<<<B_ / 8, 256>>>(x, Wg, bg);
    xconv_q<<<B_, 256>>>(x, X1, X2, sAx);

    // Weight element offsets ([N,K] packed) and n-scale offsets per expert
    const size_t off1 = 0;
    const size_t off2 = off1 + (size_t)DIN_ * H_;
    const size_t off3 = off2 + (size_t)H_ * H_;
    const size_t off4 = off3 + (size_t)H_ * H_;
    const size_t off5 = off4 + (size_t)H_ * H_;
    const int na1 = 0, na2 = 2048, na3 = 4096, na4 = 6144, na5 = 8192;

    cudaMemsetAsync(wam, 0, (size_t)NPE * E_ * sizeof(float));

    const dim3 wblk(32, 8);
    for (int e = 0; e < E_; e++) {
        const size_t eb = (size_t)e * WPE;
        float* we = wam + (size_t)e * NPE;
        wamax_kernel<<<dim3(H_ / 256, 8), 256>>>(W1 + (size_t)e * DIN_ * H_, we + na1, DIN_, H_);
        wamax_kernel<<<dim3(H_ / 256, 8), 256>>>(W2 + (size_t)e * H_ * H_, we + na2, H_, H_);
        wamax_kernel<<<dim3(H_ / 256, 8), 256>>>(W3 + (size_t)e * H_ * H_, we + na3, H_, H_);
        wamax_kernel<<<dim3(H_ / 256, 8), 256>>>(W4 + (size_t)e * H_ * H_, we + na4, H_, H_);
        wamax_kernel<<<dim3(DOUT_ / 256, 8), 256>>>(W5 + (size_t)e * H_ * DOUT_, we + na5, H_, DOUT_);
    }
    for (int e = 0; e < E_; e++) {
        const size_t eb = (size_t)e * WPE;
        float* we = wam + (size_t)e * NPE;
        wconv_q<<<dim3(H_ / 32, DIN_ / 128), wblk>>>(
            W1 + (size_t)e * DIN_ * H_, we + na1, Wq1 + eb + off1, Wq2 + eb + off1, DIN_, H_);
        wconv_q<<<dim3(H_ / 32, H_ / 128), wblk>>>(
            W2 + (size_t)e * H_ * H_, we + na2, Wq1 + eb + off2, Wq2 + eb + off2, H_, H_);
        wconv_q<<<dim3(H_ / 32, H_ / 128), wblk>>>(
            W3 + (size_t)e * H_ * H_, we + na3, Wq1 + eb + off3, Wq2 + eb + off3, H_, H_);
        wconv_q<<<dim3(H_ / 32, H_ / 128), wblk>>>(
            W4 + (size_t)e * H_ * H_, we + na4, Wq1 + eb + off4, Wq2 + eb + off4, H_, H_);
        wconv_q<<<dim3(DOUT_ / 32, H_ / 128), wblk>>>(
            W5 + (size_t)e * H_ * DOUT_, we + na5, Wq1 + eb + off5, Wq2 + eb + off5, H_, DOUT_);
    }

    const dim3 gridH(H_ / 128, B_ / 128);
    const dim3 gridO(DOUT_ / 128, B_ / 128);

    for (int e = 0; e < E_; e++) {
        const size_t eb = (size_t)e * WPE;
        float* we = wam + (size_t)e * NPE;
        const float* b1e = b1 + (size_t)e * H_;
        const float* b2e = b2 + (size_t)e * H_;
        const float* b3e = b3 + (size_t)e * H_;
        const float* b4e = b4 + (size_t)e * H_;
        const float* b5e = b5 + (size_t)e * DOUT_;

        tc_gemm<0><<<gridH, 256, GEMM_SMEM>>>(X1, X2, Wq1 + eb + off1, Wq2 + eb + off1,
                                              sAx, we + na1, b1e, Cbuf, H_, DIN_, 0, 0);
        mish_ln_q<<<B_, 256>>>(Cbuf, A1, A2, sA);
        tc_gemm<0><<<gridH, 256, GEMM_SMEM>>>(A1, A2, Wq1 + eb + off2, Wq2 + eb + off2,
                                              sA, we + na2, b2e, Cbuf, H_, H_, 0, 0);
        mish_ln_q<<<B_, 256>>>(Cbuf, A1, A2, sA);
        tc_gemm<0><<<gridH, 256, GEMM_SMEM>>>(A1, A2, Wq1 + eb + off3, Wq2 + eb + off3,
                                              sA, we + na3, b3e, Cbuf, H_, H_, 0, 0);
        mish_ln_q<<<B_, 256>>>(Cbuf, A1, A2, sA);
        tc_gemm<0><<<gridH, 256, GEMM_SMEM>>>(A1, A2, Wq1 + eb + off4, Wq2 + eb + off4,
                                              sA, we + na4, b4e, Cbuf, H_, H_, 0, 0);
        mish_ln_q<<<B_, 256>>>(Cbuf, A1, A2, sA);
        tc_gemm<1><<<gridO, 256, GEMM_SMEM>>>(A1, A2, Wq1 + eb + off5, Wq2 + eb + off5,
                                              sA, we + na5, b5e, out, DOUT_, H_,
                                              e, (e == 0) ? 1 : 0);
    }
}

// round 6
// speedup vs baseline: 2.9574x; 2.9574x over previous
#include <cuda_runtime.h>
#include <cuda_fp16.h>
#include <math.h>
#include <stdint.h>

#define B_    8192
#define DIN_  1024
#define H_    2048
#define DOUT_ 1024
#define E_    8

// ---------------------------------------------------------------------------
// Scratch (allocation-free __device__ globals)
// ---------------------------------------------------------------------------
#define WPE 16777216ull  // weight elements per expert (5 layers, transposed [N,K])
__device__ unsigned short g_Wh[WPE * E_];     // fp16 weight hi
__device__ unsigned short g_Wl[WPE * E_];     // fp16 weight lo (residual)
__device__ unsigned short g_X[(size_t)B_ * DIN_];  // fp16 activations (layer input)
__device__ unsigned short g_A[(size_t)B_ * H_];
__device__ float g_C[(size_t)B_ * H_];
__device__ float g_gate[(size_t)B_ * E_];

// ---------------------------------------------------------------------------
// PTX helpers
// ---------------------------------------------------------------------------
__device__ __forceinline__ uint32_t smem_to_u32(const void* smem_ptr) {
    uint32_t addr;
    asm("{ .reg .u64 tmp; cvta.to.shared.u64 tmp, %1; cvt.u32.u64 %0, tmp; }"
        : "=r"(addr) : "l"(smem_ptr));
    return addr;
}

#define CP_ASYNC16(dst, src) \
    asm volatile("cp.async.cg.shared.global [%0], [%1], 16;" \
                 :: "r"((uint32_t)(dst)), "l"(src) : "memory")

__device__ __forceinline__ void ldsm_x4(uint32_t* r, uint32_t addr) {
    asm volatile("ldmatrix.sync.aligned.m8n8.x4.shared.b16 {%0,%1,%2,%3}, [%4];"
                 : "=r"(r[0]), "=r"(r[1]), "=r"(r[2]), "=r"(r[3]) : "r"(addr));
}

__device__ __forceinline__ void mma_f16(float* c, const uint32_t* a, const uint32_t* b) {
    asm volatile(
        "mma.sync.aligned.m16n8k16.row.col.f32.f16.f16.f32 "
        "{%0,%1,%2,%3}, {%4,%5,%6,%7}, {%8,%9}, {%0,%1,%2,%3};"
        : "+f"(c[0]), "+f"(c[1]), "+f"(c[2]), "+f"(c[3])
        : "r"(a[0]), "r"(a[1]), "r"(a[2]), "r"(a[3]), "r"(b[0]), "r"(b[1]));
}

// ---------------------------------------------------------------------------
// Gate: softmax(x @ Wg + bg) per row. One warp/row.
// ---------------------------------------------------------------------------
__global__ void gate_kernel(const float* __restrict__ x,
                            const float* __restrict__ Wg,
                            const float* __restrict__ bg) {
    int gwarp = (blockIdx.x * blockDim.x + threadIdx.x) >> 5;
    int lane  = threadIdx.x & 31;
    if (gwarp >= B_) return;
    const float* xr = x + (size_t)gwarp * DIN_;
    float acc[E_];
#pragma unroll
    for (int e = 0; e < E_; e++) acc[e] = 0.f;
    for (int i = lane; i < DIN_; i += 32) {
        float xv = xr[i];
        const float4* w4 = reinterpret_cast<const float4*>(Wg + (size_t)i * E_);
        float4 w0 = w4[0], w1 = w4[1];
        acc[0] += xv * w0.x; acc[1] += xv * w0.y;
        acc[2] += xv * w0.z; acc[3] += xv * w0.w;
        acc[4] += xv * w1.x; acc[5] += xv * w1.y;
        acc[6] += xv * w1.z; acc[7] += xv * w1.w;
    }
#pragma unroll
    for (int e = 0; e < E_; e++) {
#pragma unroll
        for (int o = 16; o > 0; o >>= 1)
            acc[e] += __shfl_xor_sync(0xffffffffu, acc[e], o);
    }
    if (lane == 0) {
        float mx = -1e30f;
#pragma unroll
        for (int e = 0; e < E_; e++) { acc[e] += bg[e]; mx = fmaxf(mx, acc[e]); }
        float s = 0.f;
#pragma unroll
        for (int e = 0; e < E_; e++) { acc[e] = expf(acc[e] - mx); s += acc[e]; }
        float inv = 1.f / s;
#pragma unroll
        for (int e = 0; e < E_; e++) g_gate[(size_t)gwarp * E_ + e] = acc[e] * inv;
    }
}

// ---------------------------------------------------------------------------
// Weight convert+transpose: W [K,N] fp32 -> Wh/Wl [N,K] fp16 split.
// Tile 64(k) x 32(n); ushort2 stores.
// ---------------------------------------------------------------------------
__global__ void wconv_kernel(const float* __restrict__ W,
                             unsigned short* __restrict__ Wh,
                             unsigned short* __restrict__ Wl,
                             int K, int N) {
    __shared__ float t[64][33];
    const int n0 = blockIdx.x * 32, k0 = blockIdx.y * 64;
    const int tx = threadIdx.x, ty = threadIdx.y;  // 32x8
#pragma unroll
    for (int r = 0; r < 8; r++) {
        int k = ty + r * 8;
        t[k][tx] = W[(size_t)(k0 + k) * N + n0 + tx];
    }
    __syncthreads();
#pragma unroll
    for (int r = 0; r < 4; r++) {
        int n = ty + r * 8;
        float v0 = t[2 * tx][n];
        float v1 = t[2 * tx + 1][n];
        __half h0 = __float2half_rn(v0);
        __half l0 = __float2half_rn(v0 - __half2float(h0));
        __half h1 = __float2half_rn(v1);
        __half l1 = __float2half_rn(v1 - __half2float(h1));
        size_t o = (size_t)(n0 + n) * K + k0 + 2 * tx;
        *reinterpret_cast<ushort2*>(&Wh[o]) =
            make_ushort2(__half_as_ushort(h0), __half_as_ushort(h1));
        *reinterpret_cast<ushort2*>(&Wl[o]) =
            make_ushort2(__half_as_ushort(l0), __half_as_ushort(l1));
    }
}

// ---------------------------------------------------------------------------
// x convert: fp32 -> single fp16.
// ---------------------------------------------------------------------------
__global__ void xconv_kernel(const float* __restrict__ x,
                             unsigned short* __restrict__ X, int n4) {
    int i = blockIdx.x * blockDim.x + threadIdx.x;
    if (i >= n4) return;
    float4 v = reinterpret_cast<const float4*>(x)[i];
    ushort4 o;
    o.x = __half_as_ushort(__float2half_rn(v.x));
    o.y = __half_as_ushort(__float2half_rn(v.y));
    o.z = __half_as_ushort(__float2half_rn(v.z));
    o.w = __half_as_ushort(__float2half_rn(v.w));
    reinterpret_cast<ushort4*>(X)[i] = o;
}

// ---------------------------------------------------------------------------
// mish + LayerNorm + fp16 convert. Row of H_=2048, 256 threads.
// Single fused (sum, sumsq) reduction.
// ---------------------------------------------------------------------------
__global__ void mish_ln_cvt_kernel(const float* __restrict__ in,
                                   unsigned short* __restrict__ A) {
    __shared__ float sred[64];
    const int t = threadIdx.x;
    const size_t rowoff = (size_t)blockIdx.x * H_;
    const float4* p = reinterpret_cast<const float4*>(in + rowoff);
    float4 v0 = p[t], v1 = p[t + 256];
    float vals[8] = {v0.x, v0.y, v0.z, v0.w, v1.x, v1.y, v1.z, v1.w};
    float s = 0.f, q = 0.f;
#pragma unroll
    for (int i = 0; i < 8; i++) {
        float h = vals[i];
        float sp = (h > 20.f) ? h : log1pf(expf(h));
        float m = h * tanhf(sp);
        vals[i] = m;
        s += m;
        q += m * m;
    }
    // fused (s, q) block reduction
#pragma unroll
    for (int o = 16; o > 0; o >>= 1) {
        s += __shfl_xor_sync(0xffffffffu, s, o);
        q += __shfl_xor_sync(0xffffffffu, q, o);
    }
    const int w = t >> 5;
    if ((t & 31) == 0) { sred[w] = s; sred[w + 32] = q; }
    __syncthreads();
    if (t < 32) {
        float rs = (t < 8) ? sred[t] : 0.f;
        float rq = (t < 8) ? sred[t + 32] : 0.f;
#pragma unroll
        for (int o = 4; o > 0; o >>= 1) {
            rs += __shfl_xor_sync(0xffffffffu, rs, o);
            rq += __shfl_xor_sync(0xffffffffu, rq, o);
        }
        if (t == 0) { sred[0] = rs; sred[32] = rq; }
    }
    __syncthreads();
    const float mu = sred[0] * (1.f / H_);
    const float var = sred[32] * (1.f / H_) - mu * mu;
    const float inv = rsqrtf(var + 1e-5f);
    unsigned short h8[8];
#pragma unroll
    for (int i = 0; i < 8; i++)
        h8[i] = __half_as_ushort(__float2half_rn((vals[i] - mu) * inv));
    ushort4* oa = reinterpret_cast<ushort4*>(A + rowoff);
    oa[t]       = make_ushort4(h8[0], h8[1], h8[2], h8[3]);
    oa[t + 256] = make_ushort4(h8[4], h8[5], h8[6], h8[7]);
}

// ---------------------------------------------------------------------------
// HMMA fp16 2-pass GEMM. CTA 128x128, warp 64x32, K-chunk 32, 4-stage cp.async.
// A: [M,K] fp16 K-major (single). W: [N,K] fp16 hi/lo K-major.
// D = A@Wh^T + A@Wl^T, fp32 accumulate (both passes into one acc).
// MODE 0: C = D + bias[col]
// MODE 1: C (+)= gate[row,expert] * (D + bias[col])   (isFirst -> '=')
// ---------------------------------------------------------------------------
#define STRIDE_B 80                      // padded row stride in bytes
#define MAT_BYTES (128 * STRIDE_B)       // 10240
#define STAGE_BYTES (3 * MAT_BYTES)      // 30720 (A, Wh, Wl)
#define NSTAGE 4
#define GEMM_SMEM (NSTAGE * STAGE_BYTES) // 122880

__device__ __forceinline__ void copy_stage(uint32_t st, int tid, int kc, int K,
                                           const unsigned short* a,
                                           const unsigned short* bh,
                                           const unsigned short* bl) {
    const unsigned short* srcs[3] = {a, bh, bl};
#pragma unroll
    for (int m = 0; m < 3; m++) {
#pragma unroll
        for (int q = 0; q < 2; q++) {
            int c = tid * 2 + q;          // 0..511
            int row = c >> 2;             // 0..127
            int kch = c & 3;              // 16B chunk within the 64B row
            uint32_t dst = st + m * MAT_BYTES + row * STRIDE_B + kch * 16;
            const unsigned short* src = srcs[m] + (size_t)row * K + kc * 32 + kch * 8;
            CP_ASYNC16(dst, src);
        }
    }
    asm volatile("cp.async.commit_group;" ::: "memory");
}

template <int MODE>
__global__ __launch_bounds__(256, 1)
void tc_gemm(const unsigned short* __restrict__ Ag,
             const unsigned short* __restrict__ Bhg,
             const unsigned short* __restrict__ Blg,
             const float* __restrict__ bias, float* __restrict__ C,
             int N, int K, int expert, int isFirst) {
    extern __shared__ __align__(16) char dynsmem[];
    const uint32_t sbase = smem_to_u32(dynsmem);

    const int tid = threadIdx.x;
    const int wid = tid >> 5;
    const int lane = tid & 31;
    const int wm = wid & 1;       // 2 warps in M
    const int wn = wid >> 1;      // 4 warps in N
    const int KT = K >> 5;        // 32 fp16 per chunk

    const unsigned short* a  = Ag  + (size_t)(blockIdx.y * 128) * K;
    const unsigned short* bh = Bhg + (size_t)(blockIdx.x * 128) * K;
    const unsigned short* bl = Blg + (size_t)(blockIdx.x * 128) * K;

    float acc[4][4][4];
#pragma unroll
    for (int i = 0; i < 4; i++)
#pragma unroll
        for (int j = 0; j < 4; j++)
#pragma unroll
            for (int q = 0; q < 4; q++) acc[i][j][q] = 0.f;

    copy_stage(sbase + 0 * STAGE_BYTES, tid, 0, K, a, bh, bl);
    copy_stage(sbase + 1 * STAGE_BYTES, tid, 1, K, a, bh, bl);
    copy_stage(sbase + 2 * STAGE_BYTES, tid, 2, K, a, bh, bl);

    const uint32_t a_row = wm * 64 + (lane & 15);
    const uint32_t a_koff = (lane >> 4) * 16;
    const uint32_t b_row = wn * 32 + (lane >> 4) * 8 + (lane & 7);
    const uint32_t b_koff = ((lane >> 3) & 1) * 16;

    for (int kc = 0; kc < KT; kc++) {
        if (kc + 2 < KT)      asm volatile("cp.async.wait_group 2;" ::: "memory");
        else if (kc + 1 < KT) asm volatile("cp.async.wait_group 1;" ::: "memory");
        else                  asm volatile("cp.async.wait_group 0;" ::: "memory");
        __syncthreads();
        // Stage (kc-1)&3 was fully consumed before the barrier above -> refill it.
        if (kc + 3 < KT)
            copy_stage(sbase + ((kc + 3) & 3) * STAGE_BYTES, tid, kc + 3, K, a, bh, bl);

        const uint32_t st = sbase + (kc & 3) * STAGE_BYTES;
        const uint32_t A_b  = st;
        const uint32_t Bh_b = st + MAT_BYTES;
        const uint32_t Bl_b = st + 2 * MAT_BYTES;

#pragma unroll
        for (int h = 0; h < 2; h++) {     // two k16 halves of the 32-elem chunk
            const uint32_t kbyte = h * 32;
            uint32_t fa[16], fbh[8], fbl[8];
#pragma unroll
            for (int i = 0; i < 4; i++) {
                uint32_t off = (a_row + i * 16) * STRIDE_B + kbyte + a_koff;
                ldsm_x4(&fa[i * 4], A_b + off);
            }
#pragma unroll
            for (int p = 0; p < 2; p++) {
                uint32_t off = (b_row + p * 16) * STRIDE_B + kbyte + b_koff;
                ldsm_x4(&fbh[p * 4], Bh_b + off);
                ldsm_x4(&fbl[p * 4], Bl_b + off);
            }
            // 32 MMAs: pass hi then pass lo; 16 independent acc tiles per pass
#pragma unroll
            for (int i = 0; i < 4; i++)
#pragma unroll
                for (int j = 0; j < 4; j++)
                    mma_f16(acc[i][j], &fa[i * 4], &fbh[(j >> 1) * 4 + (j & 1) * 2]);
#pragma unroll
            for (int i = 0; i < 4; i++)
#pragma unroll
                for (int j = 0; j < 4; j++)
                    mma_f16(acc[i][j], &fa[i * 4], &fbl[(j >> 1) * 4 + (j & 1) * 2]);
        }
    }

    // Epilogue
    const int r0 = blockIdx.y * 128 + wm * 64 + (lane >> 2);
    const int cbase = blockIdx.x * 128 + wn * 32 + (lane & 3) * 2;
#pragma unroll
    for (int i = 0; i < 4; i++) {
        const int rowA = r0 + i * 16;
        const int rowB = rowA + 8;
        float gA = 0.f, gB = 0.f;
        if (MODE == 1) {
            gA = g_gate[(size_t)rowA * E_ + expert];
            gB = g_gate[(size_t)rowB * E_ + expert];
        }
#pragma unroll
        for (int j = 0; j < 4; j++) {
            const int col = cbase + j * 8;
            float b0 = bias[col], b1 = bias[col + 1];
            float* pA = C + (size_t)rowA * N + col;
            float* pB = C + (size_t)rowB * N + col;
            if (MODE == 0) {
                *reinterpret_cast<float2*>(pA) =
                    make_float2(acc[i][j][0] + b0, acc[i][j][1] + b1);
                *reinterpret_cast<float2*>(pB) =
                    make_float2(acc[i][j][2] + b0, acc[i][j][3] + b1);
            } else {
                float2 oA = isFirst ? make_float2(0.f, 0.f)
                                    : *reinterpret_cast<const float2*>(pA);
                float2 oB = isFirst ? make_float2(0.f, 0.f)
                                    : *reinterpret_cast<const float2*>(pB);
                oA.x += gA * (acc[i][j][0] + b0);
                oA.y += gA * (acc[i][j][1] + b1);
                oB.x += gB * (acc[i][j][2] + b0);
                oB.y += gB * (acc[i][j][3] + b1);
                *reinterpret_cast<float2*>(pA) = oA;
                *reinterpret_cast<float2*>(pB) = oB;
            }
        }
    }
}

// ---------------------------------------------------------------------------
// Launch
// ---------------------------------------------------------------------------
extern "C" void kernel_launch(void* const* d_in, const int* in_sizes, int n_in,
                              void* d_out, int out_size) {
    const float* x  = (const float*)d_in[0];
    const float* Wg = (const float*)d_in[1];
    const float* bg = (const float*)d_in[2];
    const float* W1 = (const float*)d_in[3];
    const float* b1 = (const float*)d_in[4];
    const float* W2 = (const float*)d_in[5];
    const float* b2 = (const float*)d_in[6];
    const float* W3 = (const float*)d_in[7];
    const float* b3 = (const float*)d_in[8];
    const float* W4 = (const float*)d_in[9];
    const float* b4 = (const float*)d_in[10];
    const float* W5 = (const float*)d_in[11];
    const float* b5 = (const float*)d_in[12];
    float* out = (float*)d_out;

    void *pWh, *pWl, *pX, *pA, *pC;
    cudaGetSymbolAddress(&pWh, g_Wh);
    cudaGetSymbolAddress(&pWl, g_Wl);
    cudaGetSymbolAddress(&pX, g_X);
    cudaGetSymbolAddress(&pA, g_A);
    cudaGetSymbolAddress(&pC, g_C);
    unsigned short* Wh = (unsigned short*)pWh;
    unsigned short* Wl = (unsigned short*)pWl;
    unsigned short* X = (unsigned short*)pX;
    unsigned short* A = (unsigned short*)pA;
    float* Cbuf = (float*)pC;

    cudaFuncSetAttribute(tc_gemm<0>, cudaFuncAttributeMaxDynamicSharedMemorySize, GEMM_SMEM);
    cudaFuncSetAttribute(tc_gemm<1>, cudaFuncAttributeMaxDynamicSharedMemorySize, GEMM_SMEM);

    // Weight element offsets ([N,K] packed per expert)
    const size_t off1 = 0;
    const size_t off2 = off1 + (size_t)DIN_ * H_;
    const size_t off3 = off2 + (size_t)H_ * H_;
    const size_t off4 = off3 + (size_t)H_ * H_;
    const size_t off5 = off4 + (size_t)H_ * H_;
    const size_t offs[5] = {off1, off2, off3, off4, off5};

    const dim3 wblk(32, 8);
    const dim3 gridH(H_ / 128, B_ / 128);
    const dim3 gridO(DOUT_ / 128, B_ / 128);

    // Launch order puts the first tc_gemm at graph-launch index 5 so ncu
    // (-s 5 -c 1) profiles the GEMM: gate(0), xconv(1), wconv l1-l3 of e0
    // (2,3,4), tc_gemm(5).
    gate_kernel<<<B_ / 8, 256>>>(x, Wg, bg);
    xconv_kernel<<<(B_ * DIN_ / 4 + 255) / 256, 256>>>(x, X, B_ * DIN_ / 4);

    for (int e = 0; e < E_; e++) {
        const size_t eb = (size_t)e * WPE;
        const float* Ws[5] = {W1 + (size_t)e * DIN_ * H_, W2 + (size_t)e * H_ * H_,
                              W3 + (size_t)e * H_ * H_, W4 + (size_t)e * H_ * H_,
                              W5 + (size_t)e * H_ * DOUT_};
        const float* bs[5] = {b1 + (size_t)e * H_, b2 + (size_t)e * H_,
                              b3 + (size_t)e * H_, b4 + (size_t)e * H_,
                              b5 + (size_t)e * DOUT_};
        const int Ks[5] = {DIN_, H_, H_, H_, H_};
        const int Ns[5] = {H_, H_, H_, H_, DOUT_};

        if (e == 0) {
            // wconv l1..l3 first (indices 2,3,4), gemm1 at index 5
            for (int l = 0; l < 3; l++)
                wconv_kernel<<<dim3(Ns[l] / 32, Ks[l] / 64), wblk>>>(
                    Ws[l], Wh + eb + offs[l], Wl + eb + offs[l], Ks[l], Ns[l]);
            tc_gemm<0><<<gridH, 256, GEMM_SMEM>>>(X, Wh + eb + off1, Wl + eb + off1,
                                                  bs[0], Cbuf, H_, DIN_, 0, 0);
            mish_ln_cvt_kernel<<<B_, 256>>>(Cbuf, A);
            for (int l = 3; l < 5; l++)
                wconv_kernel<<<dim3(Ns[l] / 32, Ks[l] / 64), wblk>>>(
                    Ws[l], Wh + eb + offs[l], Wl + eb + offs[l], Ks[l], Ns[l]);
        } else {
            for (int l = 0; l < 5; l++)
                wconv_kernel<<<dim3(Ns[l] / 32, Ks[l] / 64), wblk>>>(
                    Ws[l], Wh + eb + offs[l], Wl + eb + offs[l], Ks[l], Ns[l]);
            tc_gemm<0><<<gridH, 256, GEMM_SMEM>>>(X, Wh + eb + off1, Wl + eb + off1,
                                                  bs[0], Cbuf, H_, DIN_, 0, 0);
            mish_ln_cvt_kernel<<<B_, 256>>>(Cbuf, A);
        }
        tc_gemm<0><<<gridH, 256, GEMM_SMEM>>>(A, Wh + eb + off2, Wl + eb + off2,
                                              bs[1], Cbuf, H_, H_, 0, 0);
        mish_ln_cvt_kernel<<<B_, 256>>>(Cbuf, A);
        tc_gemm<0><<<gridH, 256, GEMM_SMEM>>>(A, Wh + eb + off3, Wl + eb + off3,
                                              bs[2], Cbuf, H_, H_, 0, 0);
        mish_ln_cvt_kernel<<<B_, 256>>>(Cbuf, A);
        tc_gemm<0><<<gridH, 256, GEMM_SMEM>>>(A, Wh + eb + off4, Wl + eb + off4,
                                              bs[3], Cbuf, H_, H_, 0, 0);
        mish_ln_cvt_kernel<<<B_, 256>>>(Cbuf, A);
        tc_gemm<1><<<gridO, 256, GEMM_SMEM>>>(A, Wh + eb + off5, Wl + eb + off5,
                                              bs[4], out, DOUT_, H_, e, (e == 0) ? 1 : 0);
    }
}

// round 7
// speedup vs baseline: 4.9595x; 1.6770x over previous
#include <cuda_runtime.h>
#include <cuda_fp16.h>
#include <math.h>
#include <stdint.h>

#define B_    8192
#define DIN_  1024
#define H_    2048
#define DOUT_ 1024
#define E_    8

// ---------------------------------------------------------------------------
// Scratch (allocation-free __device__ globals)
// ---------------------------------------------------------------------------
#define WPE 16777216ull  // weight elements per expert (5 layers, transposed [N,K])
__device__ unsigned short g_Wh[WPE * E_];                 // fp16 weight hi (all layers)
__device__ unsigned short g_Wl[(size_t)DIN_ * H_ * E_];   // fp16 weight lo (L1 only)
__device__ unsigned short g_X[(size_t)B_ * DIN_];         // fp16 input acts
__device__ unsigned short g_A[(size_t)B_ * H_];
__device__ float g_C[(size_t)B_ * H_];
__device__ float g_gate[(size_t)B_ * E_];

// ---------------------------------------------------------------------------
// PTX helpers
// ---------------------------------------------------------------------------
__device__ __forceinline__ uint32_t smem_to_u32(const void* smem_ptr) {
    uint32_t addr;
    asm("{ .reg .u64 tmp; cvta.to.shared.u64 tmp, %1; cvt.u32.u64 %0, tmp; }"
        : "=r"(addr) : "l"(smem_ptr));
    return addr;
}

#define CP_ASYNC16(dst, src) \
    asm volatile("cp.async.cg.shared.global [%0], [%1], 16;" \
                 :: "r"((uint32_t)(dst)), "l"(src) : "memory")

__device__ __forceinline__ void ldsm_x4(uint32_t* r, uint32_t addr) {
    asm volatile("ldmatrix.sync.aligned.m8n8.x4.shared.b16 {%0,%1,%2,%3}, [%4];"
                 : "=r"(r[0]), "=r"(r[1]), "=r"(r[2]), "=r"(r[3]) : "r"(addr));
}

__device__ __forceinline__ void mma_f16(float* c, const uint32_t* a, const uint32_t* b) {
    asm volatile(
        "mma.sync.aligned.m16n8k16.row.col.f32.f16.f16.f32 "
        "{%0,%1,%2,%3}, {%4,%5,%6,%7}, {%8,%9}, {%0,%1,%2,%3};"
        : "+f"(c[0]), "+f"(c[1]), "+f"(c[2]), "+f"(c[3])
        : "r"(a[0]), "r"(a[1]), "r"(a[2]), "r"(a[3]), "r"(b[0]), "r"(b[1]));
}

// ---------------------------------------------------------------------------
// Gate: softmax(x @ Wg + bg) per row. One warp/row.
// ---------------------------------------------------------------------------
__global__ void gate_kernel(const float* __restrict__ x,
                            const float* __restrict__ Wg,
                            const float* __restrict__ bg) {
    int gwarp = (blockIdx.x * blockDim.x + threadIdx.x) >> 5;
    int lane  = threadIdx.x & 31;
    if (gwarp >= B_) return;
    const float* xr = x + (size_t)gwarp * DIN_;
    float acc[E_];
#pragma unroll
    for (int e = 0; e < E_; e++) acc[e] = 0.f;
    for (int i = lane; i < DIN_; i += 32) {
        float xv = xr[i];
        const float4* w4 = reinterpret_cast<const float4*>(Wg + (size_t)i * E_);
        float4 w0 = w4[0], w1 = w4[1];
        acc[0] += xv * w0.x; acc[1] += xv * w0.y;
        acc[2] += xv * w0.z; acc[3] += xv * w0.w;
        acc[4] += xv * w1.x; acc[5] += xv * w1.y;
        acc[6] += xv * w1.z; acc[7] += xv * w1.w;
    }
#pragma unroll
    for (int e = 0; e < E_; e++) {
#pragma unroll
        for (int o = 16; o > 0; o >>= 1)
            acc[e] += __shfl_xor_sync(0xffffffffu, acc[e], o);
    }
    if (lane == 0) {
        float mx = -1e30f;
#pragma unroll
        for (int e = 0; e < E_; e++) { acc[e] += bg[e]; mx = fmaxf(mx, acc[e]); }
        float s = 0.f;
#pragma unroll
        for (int e = 0; e < E_; e++) { acc[e] = expf(acc[e] - mx); s += acc[e]; }
        float inv = 1.f / s;
#pragma unroll
        for (int e = 0; e < E_; e++) g_gate[(size_t)gwarp * E_ + e] = acc[e] * inv;
    }
}

// ---------------------------------------------------------------------------
// Weight convert+transpose, dual (hi+lo): W [K,N] fp32 -> [N,K] fp16 hi/lo.
// ---------------------------------------------------------------------------
__global__ void wconv_dual(const float* __restrict__ W,
                           unsigned short* __restrict__ Wh,
                           unsigned short* __restrict__ Wl,
                           int K, int N) {
    __shared__ float t[64][33];
    const int n0 = blockIdx.x * 32, k0 = blockIdx.y * 64;
    const int tx = threadIdx.x, ty = threadIdx.y;  // 32x8
#pragma unroll
    for (int r = 0; r < 8; r++) {
        int k = ty + r * 8;
        t[k][tx] = W[(size_t)(k0 + k) * N + n0 + tx];
    }
    __syncthreads();
#pragma unroll
    for (int r = 0; r < 4; r++) {
        int n = ty + r * 8;
        float v0 = t[2 * tx][n];
        float v1 = t[2 * tx + 1][n];
        __half h0 = __float2half_rn(v0);
        __half l0 = __float2half_rn(v0 - __half2float(h0));
        __half h1 = __float2half_rn(v1);
        __half l1 = __float2half_rn(v1 - __half2float(h1));
        size_t o = (size_t)(n0 + n) * K + k0 + 2 * tx;
        *reinterpret_cast<ushort2*>(&Wh[o]) =
            make_ushort2(__half_as_ushort(h0), __half_as_ushort(h1));
        *reinterpret_cast<ushort2*>(&Wl[o]) =
            make_ushort2(__half_as_ushort(l0), __half_as_ushort(l1));
    }
}

// ---------------------------------------------------------------------------
// Weight convert+transpose, hi only: W [K,N] fp32 -> [N,K] fp16.
// ---------------------------------------------------------------------------
__global__ void wconv_hi(const float* __restrict__ W,
                         unsigned short* __restrict__ Wh,
                         int K, int N) {
    __shared__ float t[64][33];
    const int n0 = blockIdx.x * 32, k0 = blockIdx.y * 64;
    const int tx = threadIdx.x, ty = threadIdx.y;  // 32x8
#pragma unroll
    for (int r = 0; r < 8; r++) {
        int k = ty + r * 8;
        t[k][tx] = W[(size_t)(k0 + k) * N + n0 + tx];
    }
    __syncthreads();
#pragma unroll
    for (int r = 0; r < 4; r++) {
        int n = ty + r * 8;
        __half h0 = __float2half_rn(t[2 * tx][n]);
        __half h1 = __float2half_rn(t[2 * tx + 1][n]);
        size_t o = (size_t)(n0 + n) * K + k0 + 2 * tx;
        *reinterpret_cast<ushort2*>(&Wh[o]) =
            make_ushort2(__half_as_ushort(h0), __half_as_ushort(h1));
    }
}

// ---------------------------------------------------------------------------
// x convert: fp32 -> single fp16.
// ---------------------------------------------------------------------------
__global__ void xconv_kernel(const float* __restrict__ x,
                             unsigned short* __restrict__ X, int n4) {
    int i = blockIdx.x * blockDim.x + threadIdx.x;
    if (i >= n4) return;
    float4 v = reinterpret_cast<const float4*>(x)[i];
    ushort4 o;
    o.x = __half_as_ushort(__float2half_rn(v.x));
    o.y = __half_as_ushort(__float2half_rn(v.y));
    o.z = __half_as_ushort(__float2half_rn(v.z));
    o.w = __half_as_ushort(__float2half_rn(v.w));
    reinterpret_cast<ushort4*>(X)[i] = o;
}

// ---------------------------------------------------------------------------
// mish + LayerNorm + fp16 convert. Row of H_=2048, 256 threads.
// ---------------------------------------------------------------------------
__global__ void mish_ln_cvt_kernel(const float* __restrict__ in,
                                   unsigned short* __restrict__ A) {
    __shared__ float sred[64];
    const int t = threadIdx.x;
    const size_t rowoff = (size_t)blockIdx.x * H_;
    const float4* p = reinterpret_cast<const float4*>(in + rowoff);
    float4 v0 = p[t], v1 = p[t + 256];
    float vals[8] = {v0.x, v0.y, v0.z, v0.w, v1.x, v1.y, v1.z, v1.w};
    float s = 0.f, q = 0.f;
#pragma unroll
    for (int i = 0; i < 8; i++) {
        float h = vals[i];
        float sp = (h > 20.f) ? h : log1pf(expf(h));
        float m = h * tanhf(sp);
        vals[i] = m;
        s += m;
        q += m * m;
    }
#pragma unroll
    for (int o = 16; o > 0; o >>= 1) {
        s += __shfl_xor_sync(0xffffffffu, s, o);
        q += __shfl_xor_sync(0xffffffffu, q, o);
    }
    const int w = t >> 5;
    if ((t & 31) == 0) { sred[w] = s; sred[w + 32] = q; }
    __syncthreads();
    if (t < 32) {
        float rs = (t < 8) ? sred[t] : 0.f;
        float rq = (t < 8) ? sred[t + 32] : 0.f;
#pragma unroll
        for (int o = 4; o > 0; o >>= 1) {
            rs += __shfl_xor_sync(0xffffffffu, rs, o);
            rq += __shfl_xor_sync(0xffffffffu, rq, o);
        }
        if (t == 0) { sred[0] = rs; sred[32] = rq; }
    }
    __syncthreads();
    const float mu = sred[0] * (1.f / H_);
    const float var = sred[32] * (1.f / H_) - mu * mu;
    const float inv = rsqrtf(var + 1e-5f);
    unsigned short h8[8];
#pragma unroll
    for (int i = 0; i < 8; i++)
        h8[i] = __half_as_ushort(__float2half_rn((vals[i] - mu) * inv));
    ushort4* oa = reinterpret_cast<ushort4*>(A + rowoff);
    oa[t]       = make_ushort4(h8[0], h8[1], h8[2], h8[3]);
    oa[t + 256] = make_ushort4(h8[4], h8[5], h8[6], h8[7]);
}

// ---------------------------------------------------------------------------
// Shared GEMM geometry
// ---------------------------------------------------------------------------
#define STRIDE_B 80                      // padded row stride in bytes
#define MAT_BYTES (128 * STRIDE_B)       // 10240
#define NSTAGE 4
#define DUAL_STAGE (3 * MAT_BYTES)       // A, Wh, Wl
#define DUAL_SMEM (NSTAGE * DUAL_STAGE)  // 122880
#define SGL_STAGE (2 * MAT_BYTES)        // A, Wh
#define SGL_SMEM (NSTAGE * SGL_STAGE)    // 81920

template <int NMAT>
__device__ __forceinline__ void copy_stage(uint32_t st, int tid, int kc, int K,
                                           const unsigned short* a,
                                           const unsigned short* bh,
                                           const unsigned short* bl) {
    const unsigned short* srcs[3] = {a, bh, bl};
#pragma unroll
    for (int m = 0; m < NMAT; m++) {
#pragma unroll
        for (int q = 0; q < 2; q++) {
            int c = tid * 2 + q;          // 0..511
            int row = c >> 2;             // 0..127
            int kch = c & 3;              // 16B chunk within the 64B row
            uint32_t dst = st + m * MAT_BYTES + row * STRIDE_B + kch * 16;
            const unsigned short* src = srcs[m] + (size_t)row * K + kc * 32 + kch * 8;
            CP_ASYNC16(dst, src);
        }
    }
    asm volatile("cp.async.commit_group;" ::: "memory");
}

// ---------------------------------------------------------------------------
// Dual-pass GEMM (L1 only): D = A@Wh^T + A@Wl^T. C = D + bias.
// ---------------------------------------------------------------------------
__global__ __launch_bounds__(256, 1)
void tc_gemm_dual(const unsigned short* __restrict__ Ag,
                  const unsigned short* __restrict__ Bhg,
                  const unsigned short* __restrict__ Blg,
                  const float* __restrict__ bias, float* __restrict__ C,
                  int N, int K) {
    extern __shared__ __align__(16) char dynsmem[];
    const uint32_t sbase = smem_to_u32(dynsmem);
    const int tid = threadIdx.x;
    const int wid = tid >> 5, lane = tid & 31;
    const int wm = wid & 1, wn = wid >> 1;
    const int KT = K >> 5;

    const unsigned short* a  = Ag  + (size_t)(blockIdx.y * 128) * K;
    const unsigned short* bh = Bhg + (size_t)(blockIdx.x * 128) * K;
    const unsigned short* bl = Blg + (size_t)(blockIdx.x * 128) * K;

    float acc[4][4][4];
#pragma unroll
    for (int i = 0; i < 4; i++)
#pragma unroll
        for (int j = 0; j < 4; j++)
#pragma unroll
            for (int q = 0; q < 4; q++) acc[i][j][q] = 0.f;

    copy_stage<3>(sbase + 0 * DUAL_STAGE, tid, 0, K, a, bh, bl);
    copy_stage<3>(sbase + 1 * DUAL_STAGE, tid, 1, K, a, bh, bl);
    copy_stage<3>(sbase + 2 * DUAL_STAGE, tid, 2, K, a, bh, bl);

    const uint32_t a_row = wm * 64 + (lane & 15);
    const uint32_t a_koff = (lane >> 4) * 16;
    const uint32_t b_row = wn * 32 + (lane >> 4) * 8 + (lane & 7);
    const uint32_t b_koff = ((lane >> 3) & 1) * 16;

    for (int kc = 0; kc < KT; kc++) {
        if (kc + 2 < KT)      asm volatile("cp.async.wait_group 2;" ::: "memory");
        else if (kc + 1 < KT) asm volatile("cp.async.wait_group 1;" ::: "memory");
        else                  asm volatile("cp.async.wait_group 0;" ::: "memory");
        __syncthreads();
        if (kc + 3 < KT)
            copy_stage<3>(sbase + ((kc + 3) & 3) * DUAL_STAGE, tid, kc + 3, K, a, bh, bl);

        const uint32_t st = sbase + (kc & 3) * DUAL_STAGE;
#pragma unroll
        for (int h = 0; h < 2; h++) {
            const uint32_t kbyte = h * 32;
            uint32_t fa[16], fbh[8], fbl[8];
#pragma unroll
            for (int i = 0; i < 4; i++)
                ldsm_x4(&fa[i * 4], st + (a_row + i * 16) * STRIDE_B + kbyte + a_koff);
#pragma unroll
            for (int p = 0; p < 2; p++) {
                uint32_t off = (b_row + p * 16) * STRIDE_B + kbyte + b_koff;
                ldsm_x4(&fbh[p * 4], st + MAT_BYTES + off);
                ldsm_x4(&fbl[p * 4], st + 2 * MAT_BYTES + off);
            }
#pragma unroll
            for (int i = 0; i < 4; i++)
#pragma unroll
                for (int j = 0; j < 4; j++)
                    mma_f16(acc[i][j], &fa[i * 4], &fbh[(j >> 1) * 4 + (j & 1) * 2]);
#pragma unroll
            for (int i = 0; i < 4; i++)
#pragma unroll
                for (int j = 0; j < 4; j++)
                    mma_f16(acc[i][j], &fa[i * 4], &fbl[(j >> 1) * 4 + (j & 1) * 2]);
        }
    }

    const int r0 = blockIdx.y * 128 + wm * 64 + (lane >> 2);
    const int cbase = blockIdx.x * 128 + wn * 32 + (lane & 3) * 2;
#pragma unroll
    for (int i = 0; i < 4; i++) {
        const int rowA = r0 + i * 16;
        const int rowB = rowA + 8;
#pragma unroll
        for (int j = 0; j < 4; j++) {
            const int col = cbase + j * 8;
            float b0 = bias[col], b1 = bias[col + 1];
            *reinterpret_cast<float2*>(C + (size_t)rowA * N + col) =
                make_float2(acc[i][j][0] + b0, acc[i][j][1] + b1);
            *reinterpret_cast<float2*>(C + (size_t)rowB * N + col) =
                make_float2(acc[i][j][2] + b0, acc[i][j][3] + b1);
        }
    }
}

// ---------------------------------------------------------------------------
// Single-pass GEMM (L2..L5): D = A@Wh^T. 2 CTAs/SM.
// MODE 0: C = D + bias. MODE 1: C (+)= gate * (D + bias).
// ---------------------------------------------------------------------------
template <int MODE>
__global__ __launch_bounds__(256, 2)
void tc_gemm_single(const unsigned short* __restrict__ Ag,
                    const unsigned short* __restrict__ Bhg,
                    const float* __restrict__ bias, float* __restrict__ C,
                    int N, int K, int expert, int isFirst) {
    extern __shared__ __align__(16) char dynsmem[];
    const uint32_t sbase = smem_to_u32(dynsmem);
    const int tid = threadIdx.x;
    const int wid = tid >> 5, lane = tid & 31;
    const int wm = wid & 1, wn = wid >> 1;
    const int KT = K >> 5;

    const unsigned short* a  = Ag  + (size_t)(blockIdx.y * 128) * K;
    const unsigned short* bh = Bhg + (size_t)(blockIdx.x * 128) * K;

    float acc[4][4][4];
#pragma unroll
    for (int i = 0; i < 4; i++)
#pragma unroll
        for (int j = 0; j < 4; j++)
#pragma unroll
            for (int q = 0; q < 4; q++) acc[i][j][q] = 0.f;

    copy_stage<2>(sbase + 0 * SGL_STAGE, tid, 0, K, a, bh, 0);
    copy_stage<2>(sbase + 1 * SGL_STAGE, tid, 1, K, a, bh, 0);
    copy_stage<2>(sbase + 2 * SGL_STAGE, tid, 2, K, a, bh, 0);

    const uint32_t a_row = wm * 64 + (lane & 15);
    const uint32_t a_koff = (lane >> 4) * 16;
    const uint32_t b_row = wn * 32 + (lane >> 4) * 8 + (lane & 7);
    const uint32_t b_koff = ((lane >> 3) & 1) * 16;

    for (int kc = 0; kc < KT; kc++) {
        if (kc + 2 < KT)      asm volatile("cp.async.wait_group 2;" ::: "memory");
        else if (kc + 1 < KT) asm volatile("cp.async.wait_group 1;" ::: "memory");
        else                  asm volatile("cp.async.wait_group 0;" ::: "memory");
        __syncthreads();
        if (kc + 3 < KT)
            copy_stage<2>(sbase + ((kc + 3) & 3) * SGL_STAGE, tid, kc + 3, K, a, bh, 0);

        const uint32_t st = sbase + (kc & 3) * SGL_STAGE;
#pragma unroll
        for (int h = 0; h < 2; h++) {
            const uint32_t kbyte = h * 32;
            uint32_t fa[16], fbh[8];
#pragma unroll
            for (int i = 0; i < 4; i++)
                ldsm_x4(&fa[i * 4], st + (a_row + i * 16) * STRIDE_B + kbyte + a_koff);
#pragma unroll
            for (int p = 0; p < 2; p++)
                ldsm_x4(&fbh[p * 4],
                        st + MAT_BYTES + (b_row + p * 16) * STRIDE_B + kbyte + b_koff);
#pragma unroll
            for (int i = 0; i < 4; i++)
#pragma unroll
                for (int j = 0; j < 4; j++)
                    mma_f16(acc[i][j], &fa[i * 4], &fbh[(j >> 1) * 4 + (j & 1) * 2]);
        }
    }

    const int r0 = blockIdx.y * 128 + wm * 64 + (lane >> 2);
    const int cbase = blockIdx.x * 128 + wn * 32 + (lane & 3) * 2;
#pragma unroll
    for (int i = 0; i < 4; i++) {
        const int rowA = r0 + i * 16;
        const int rowB = rowA + 8;
        float gA = 0.f, gB = 0.f;
        if (MODE == 1) {
            gA = g_gate[(size_t)rowA * E_ + expert];
            gB = g_gate[(size_t)rowB * E_ + expert];
        }
#pragma unroll
        for (int j = 0; j < 4; j++) {
            const int col = cbase + j * 8;
            float b0 = bias[col], b1 = bias[col + 1];
            float* pA = C + (size_t)rowA * N + col;
            float* pB = C + (size_t)rowB * N + col;
            if (MODE == 0) {
                *reinterpret_cast<float2*>(pA) =
                    make_float2(acc[i][j][0] + b0, acc[i][j][1] + b1);
                *reinterpret_cast<float2*>(pB) =
                    make_float2(acc[i][j][2] + b0, acc[i][j][3] + b1);
            } else {
                float2 oA = isFirst ? make_float2(0.f, 0.f)
                                    : *reinterpret_cast<const float2*>(pA);
                float2 oB = isFirst ? make_float2(0.f, 0.f)
                                    : *reinterpret_cast<const float2*>(pB);
                oA.x += gA * (acc[i][j][0] + b0);
                oA.y += gA * (acc[i][j][1] + b1);
                oB.x += gB * (acc[i][j][2] + b0);
                oB.y += gB * (acc[i][j][3] + b1);
                *reinterpret_cast<float2*>(pA) = oA;
                *reinterpret_cast<float2*>(pB) = oB;
            }
        }
    }
}

// ---------------------------------------------------------------------------
// Launch
// ---------------------------------------------------------------------------
extern "C" void kernel_launch(void* const* d_in, const int* in_sizes, int n_in,
                              void* d_out, int out_size) {
    const float* x  = (const float*)d_in[0];
    const float* Wg = (const float*)d_in[1];
    const float* bg = (const float*)d_in[2];
    const float* W1 = (const float*)d_in[3];
    const float* b1 = (const float*)d_in[4];
    const float* W2 = (const float*)d_in[5];
    const float* b2 = (const float*)d_in[6];
    const float* W3 = (const float*)d_in[7];
    const float* b3 = (const float*)d_in[8];
    const float* W4 = (const float*)d_in[9];
    const float* b4 = (const float*)d_in[10];
    const float* W5 = (const float*)d_in[11];
    const float* b5 = (const float*)d_in[12];
    float* out = (float*)d_out;

    void *pWh, *pWl, *pX, *pA, *pC;
    cudaGetSymbolAddress(&pWh, g_Wh);
    cudaGetSymbolAddress(&pWl, g_Wl);
    cudaGetSymbolAddress(&pX, g_X);
    cudaGetSymbolAddress(&pA, g_A);
    cudaGetSymbolAddress(&pC, g_C);
    unsigned short* Wh = (unsigned short*)pWh;
    unsigned short* Wl = (unsigned short*)pWl;
    unsigned short* X = (unsigned short*)pX;
    unsigned short* A = (unsigned short*)pA;
    float* Cbuf = (float*)pC;

    cudaFuncSetAttribute(tc_gemm_dual, cudaFuncAttributeMaxDynamicSharedMemorySize, DUAL_SMEM);
    cudaFuncSetAttribute(tc_gemm_single<0>, cudaFuncAttributeMaxDynamicSharedMemorySize, SGL_SMEM);
    cudaFuncSetAttribute(tc_gemm_single<1>, cudaFuncAttributeMaxDynamicSharedMemorySize, SGL_SMEM);

    const size_t off1 = 0;
    const size_t off2 = off1 + (size_t)DIN_ * H_;
    const size_t off3 = off2 + (size_t)H_ * H_;
    const size_t off4 = off3 + (size_t)H_ * H_;
    const size_t off5 = off4 + (size_t)H_ * H_;

    const dim3 wblk(32, 8);
    const dim3 gridH(H_ / 128, B_ / 128);
    const dim3 gridO(DOUT_ / 128, B_ / 128);

    // ncu -s 5 -c 1 profiles launch index 5 => tc_gemm_single<0> (L2, e0):
    // 0: wconv_dual L1(e0), 1: wconv_hi L2(e0), 2: xconv, 3: gemm1 dual,
    // 4: mish1, 5: gemm2 single.
    {
        const size_t eb = 0;
        wconv_dual<<<dim3(H_ / 32, DIN_ / 64), wblk>>>(W1, Wh + off1, Wl, DIN_, H_);
        wconv_hi<<<dim3(H_ / 32, H_ / 64), wblk>>>(W2, Wh + off2, H_, H_);
        xconv_kernel<<<(B_ * DIN_ / 4 + 255) / 256, 256>>>(x, X, B_ * DIN_ / 4);
        tc_gemm_dual<<<gridH, 256, DUAL_SMEM>>>(X, Wh + off1, Wl, b1, Cbuf, H_, DIN_);
        mish_ln_cvt_kernel<<<B_, 256>>>(Cbuf, A);
        tc_gemm_single<0><<<gridH, 256, SGL_SMEM>>>(A, Wh + off2, b2, Cbuf, H_, H_, 0, 0);
        gate_kernel<<<B_ / 8, 256>>>(x, Wg, bg);
        wconv_hi<<<dim3(H_ / 32, H_ / 64), wblk>>>(W3, Wh + off3, H_, H_);
        wconv_hi<<<dim3(H_ / 32, H_ / 64), wblk>>>(W4, Wh + off4, H_, H_);
        wconv_hi<<<dim3(DOUT_ / 32, H_ / 64), wblk>>>(W5, Wh + off5, H_, DOUT_);
        mish_ln_cvt_kernel<<<B_, 256>>>(Cbuf, A);
        tc_gemm_single<0><<<gridH, 256, SGL_SMEM>>>(A, Wh + off3, b3, Cbuf, H_, H_, 0, 0);
        mish_ln_cvt_kernel<<<B_, 256>>>(Cbuf, A);
        tc_gemm_single<0><<<gridH, 256, SGL_SMEM>>>(A, Wh + off4, b4, Cbuf, H_, H_, 0, 0);
        mish_ln_cvt_kernel<<<B_, 256>>>(Cbuf, A);
        tc_gemm_single<1><<<gridO, 256, SGL_SMEM>>>(A, Wh + off5, b5, out, DOUT_, H_, 0, 1);
    }

    for (int e = 1; e < E_; e++) {
        const size_t eb = (size_t)e * WPE;
        unsigned short* Wle = Wl + (size_t)e * DIN_ * H_;
        const float* W1e = W1 + (size_t)e * DIN_ * H_;
        const float* W2e = W2 + (size_t)e * H_ * H_;
        const float* W3e = W3 + (size_t)e * H_ * H_;
        const float* W4e = W4 + (size_t)e * H_ * H_;
        const float* W5e = W5 + (size_t)e * H_ * DOUT_;
        const float* b1e = b1 + (size_t)e * H_;
        const float* b2e = b2 + (size_t)e * H_;
        const float* b3e = b3 + (size_t)e * H_;
        const float* b4e = b4 + (size_t)e * H_;
        const float* b5e = b5 + (size_t)e * DOUT_;

        wconv_dual<<<dim3(H_ / 32, DIN_ / 64), wblk>>>(W1e, Wh + eb + off1, Wle, DIN_, H_);
        wconv_hi<<<dim3(H_ / 32, H_ / 64), wblk>>>(W2e, Wh + eb + off2, H_, H_);
        wconv_hi<<<dim3(H_ / 32, H_ / 64), wblk>>>(W3e, Wh + eb + off3, H_, H_);
        wconv_hi<<<dim3(H_ / 32, H_ / 64), wblk>>>(W4e, Wh + eb + off4, H_, H_);
        wconv_hi<<<dim3(DOUT_ / 32, H_ / 64), wblk>>>(W5e, Wh + eb + off5, H_, DOUT_);

        tc_gemm_dual<<<gridH, 256, DUAL_SMEM>>>(X, Wh + eb + off1, Wle, b1e, Cbuf, H_, DIN_);
        mish_ln_cvt_kernel<<<B_, 256>>>(Cbuf, A);
        tc_gemm_single<0><<<gridH, 256, SGL_SMEM>>>(A, Wh + eb + off2, b2e, Cbuf, H_, H_, 0, 0);
        mish_ln_cvt_kernel<<<B_, 256>>>(Cbuf, A);
        tc_gemm_single<0><<<gridH, 256, SGL_SMEM>>>(A, Wh + eb + off3, b3e, Cbuf, H_, H_, 0, 0);
        mish_ln_cvt_kernel<<<B_, 256>>>(Cbuf, A);
        tc_gemm_single<0><<<gridH, 256, SGL_SMEM>>>(A, Wh + eb + off4, b4e, Cbuf, H_, H_, 0, 0);
        mish_ln_cvt_kernel<<<B_, 256>>>(Cbuf, A);
        tc_gemm_single<1><<<gridO, 256, SGL_SMEM>>>(A, Wh + eb + off5, b5e, out, DOUT_, H_, e, 0);
    }
}

// round 8
// speedup vs baseline: 5.7846x; 1.1664x over previous
#include <cuda_runtime.h>
#include <cuda_fp16.h>
#include <math.h>
#include <stdint.h>

#define B_    8192
#define DIN_  1024
#define H_    2048
#define DOUT_ 1024
#define E_    8

// ---------------------------------------------------------------------------
// Scratch (allocation-free __device__ globals)
// ---------------------------------------------------------------------------
#define WPE 16777216ull  // weight elements per expert (5 layers, transposed [N,K])
__device__ unsigned short g_Wh[WPE * E_];          // fp16 weights (all layers)
__device__ unsigned short g_X[(size_t)B_ * DIN_];  // fp16 input acts
__device__ unsigned short g_A[(size_t)B_ * H_];
__device__ float g_C[(size_t)B_ * H_];
__device__ float g_gate[(size_t)B_ * E_];

// ---------------------------------------------------------------------------
// PTX helpers
// ---------------------------------------------------------------------------
__device__ __forceinline__ uint32_t smem_to_u32(const void* smem_ptr) {
    uint32_t addr;
    asm("{ .reg .u64 tmp; cvta.to.shared.u64 tmp, %1; cvt.u32.u64 %0, tmp; }"
        : "=r"(addr) : "l"(smem_ptr));
    return addr;
}

#define CP_ASYNC16(dst, src) \
    asm volatile("cp.async.cg.shared.global [%0], [%1], 16;" \
                 :: "r"((uint32_t)(dst)), "l"(src) : "memory")

__device__ __forceinline__ void ldsm_x4(uint32_t* r, uint32_t addr) {
    asm volatile("ldmatrix.sync.aligned.m8n8.x4.shared.b16 {%0,%1,%2,%3}, [%4];"
                 : "=r"(r[0]), "=r"(r[1]), "=r"(r[2]), "=r"(r[3]) : "r"(addr));
}

__device__ __forceinline__ void mma_f16(float* c, const uint32_t* a, const uint32_t* b) {
    asm volatile(
        "mma.sync.aligned.m16n8k16.row.col.f32.f16.f16.f32 "
        "{%0,%1,%2,%3}, {%4,%5,%6,%7}, {%8,%9}, {%0,%1,%2,%3};"
        : "+f"(c[0]), "+f"(c[1]), "+f"(c[2]), "+f"(c[3])
        : "r"(a[0]), "r"(a[1]), "r"(a[2]), "r"(a[3]), "r"(b[0]), "r"(b[1]));
}

// ---------------------------------------------------------------------------
// Gate: softmax(x @ Wg + bg) per row. One warp/row.
// ---------------------------------------------------------------------------
__global__ void gate_kernel(const float* __restrict__ x,
                            const float* __restrict__ Wg,
                            const float* __restrict__ bg) {
    int gwarp = (blockIdx.x * blockDim.x + threadIdx.x) >> 5;
    int lane  = threadIdx.x & 31;
    if (gwarp >= B_) return;
    const float* xr = x + (size_t)gwarp * DIN_;
    float acc[E_];
#pragma unroll
    for (int e = 0; e < E_; e++) acc[e] = 0.f;
    for (int i = lane; i < DIN_; i += 32) {
        float xv = xr[i];
        const float4* w4 = reinterpret_cast<const float4*>(Wg + (size_t)i * E_);
        float4 w0 = w4[0], w1 = w4[1];
        acc[0] += xv * w0.x; acc[1] += xv * w0.y;
        acc[2] += xv * w0.z; acc[3] += xv * w0.w;
        acc[4] += xv * w1.x; acc[5] += xv * w1.y;
        acc[6] += xv * w1.z; acc[7] += xv * w1.w;
    }
#pragma unroll
    for (int e = 0; e < E_; e++) {
#pragma unroll
        for (int o = 16; o > 0; o >>= 1)
            acc[e] += __shfl_xor_sync(0xffffffffu, acc[e], o);
    }
    if (lane == 0) {
        float mx = -1e30f;
#pragma unroll
        for (int e = 0; e < E_; e++) { acc[e] += bg[e]; mx = fmaxf(mx, acc[e]); }
        float s = 0.f;
#pragma unroll
        for (int e = 0; e < E_; e++) { acc[e] = expf(acc[e] - mx); s += acc[e]; }
        float inv = 1.f / s;
#pragma unroll
        for (int e = 0; e < E_; e++) g_gate[(size_t)gwarp * E_ + e] = acc[e] * inv;
    }
}

// ---------------------------------------------------------------------------
// Weight convert+transpose: W [K,N] fp32 -> [N,K] fp16.
// ---------------------------------------------------------------------------
__global__ void wconv_hi(const float* __restrict__ W,
                         unsigned short* __restrict__ Wh,
                         int K, int N) {
    __shared__ float t[64][33];
    const int n0 = blockIdx.x * 32, k0 = blockIdx.y * 64;
    const int tx = threadIdx.x, ty = threadIdx.y;  // 32x8
#pragma unroll
    for (int r = 0; r < 8; r++) {
        int k = ty + r * 8;
        t[k][tx] = W[(size_t)(k0 + k) * N + n0 + tx];
    }
    __syncthreads();
#pragma unroll
    for (int r = 0; r < 4; r++) {
        int n = ty + r * 8;
        __half h0 = __float2half_rn(t[2 * tx][n]);
        __half h1 = __float2half_rn(t[2 * tx + 1][n]);
        size_t o = (size_t)(n0 + n) * K + k0 + 2 * tx;
        *reinterpret_cast<ushort2*>(&Wh[o]) =
            make_ushort2(__half_as_ushort(h0), __half_as_ushort(h1));
    }
}

// ---------------------------------------------------------------------------
// x convert: fp32 -> fp16.
// ---------------------------------------------------------------------------
__global__ void xconv_kernel(const float* __restrict__ x,
                             unsigned short* __restrict__ X, int n4) {
    int i = blockIdx.x * blockDim.x + threadIdx.x;
    if (i >= n4) return;
    float4 v = reinterpret_cast<const float4*>(x)[i];
    ushort4 o;
    o.x = __half_as_ushort(__float2half_rn(v.x));
    o.y = __half_as_ushort(__float2half_rn(v.y));
    o.z = __half_as_ushort(__float2half_rn(v.z));
    o.w = __half_as_ushort(__float2half_rn(v.w));
    reinterpret_cast<ushort4*>(X)[i] = o;
}

// ---------------------------------------------------------------------------
// Fast mish via exact identity:
//   tanh(softplus(h)) = (u^2 + 2u) / (u^2 + 2u + 2),  u = e^h
// One __expf + one __fdividef. h > 20 passthrough (also guards u^2 overflow).
// ---------------------------------------------------------------------------
__device__ __forceinline__ float mish_fast(float h) {
    if (h > 20.f) return h;
    float u = __expf(h);
    float w = u * (u + 2.f);
    return h * __fdividef(w, w + 2.f);
}

// ---------------------------------------------------------------------------
// mish + LayerNorm + fp16 convert. Row of H_=2048, 256 threads.
// ---------------------------------------------------------------------------
__global__ void mish_ln_cvt_kernel(const float* __restrict__ in,
                                   unsigned short* __restrict__ A) {
    __shared__ float sred[64];
    const int t = threadIdx.x;
    const size_t rowoff = (size_t)blockIdx.x * H_;
    const float4* p = reinterpret_cast<const float4*>(in + rowoff);
    float4 v0 = p[t], v1 = p[t + 256];
    float vals[8] = {v0.x, v0.y, v0.z, v0.w, v1.x, v1.y, v1.z, v1.w};
    float s = 0.f, q = 0.f;
#pragma unroll
    for (int i = 0; i < 8; i++) {
        float m = mish_fast(vals[i]);
        vals[i] = m;
        s += m;
        q += m * m;
    }
#pragma unroll
    for (int o = 16; o > 0; o >>= 1) {
        s += __shfl_xor_sync(0xffffffffu, s, o);
        q += __shfl_xor_sync(0xffffffffu, q, o);
    }
    const int w = t >> 5;
    if ((t & 31) == 0) { sred[w] = s; sred[w + 32] = q; }
    __syncthreads();
    if (t < 32) {
        float rs = (t < 8) ? sred[t] : 0.f;
        float rq = (t < 8) ? sred[t + 32] : 0.f;
#pragma unroll
        for (int o = 4; o > 0; o >>= 1) {
            rs += __shfl_xor_sync(0xffffffffu, rs, o);
            rq += __shfl_xor_sync(0xffffffffu, rq, o);
        }
        if (t == 0) { sred[0] = rs; sred[32] = rq; }
    }
    __syncthreads();
    const float mu = sred[0] * (1.f / H_);
    const float var = sred[32] * (1.f / H_) - mu * mu;
    const float inv = rsqrtf(var + 1e-5f);
    unsigned short h8[8];
#pragma unroll
    for (int i = 0; i < 8; i++)
        h8[i] = __half_as_ushort(__float2half_rn((vals[i] - mu) * inv));
    ushort4* oa = reinterpret_cast<ushort4*>(A + rowoff);
    oa[t]       = make_ushort4(h8[0], h8[1], h8[2], h8[3]);
    oa[t + 256] = make_ushort4(h8[4], h8[5], h8[6], h8[7]);
}

// ---------------------------------------------------------------------------
// GEMM geometry
// ---------------------------------------------------------------------------
#define STRIDE_B 80                      // padded row stride in bytes
#define MAT_BYTES (128 * STRIDE_B)       // 10240
#define NSTAGE 4
#define SGL_STAGE (2 * MAT_BYTES)        // A, Wh
#define SGL_SMEM (NSTAGE * SGL_STAGE)    // 81920

__device__ __forceinline__ void copy_stage2(uint32_t st, int tid, int kc, int K,
                                            const unsigned short* a,
                                            const unsigned short* bh) {
    const unsigned short* srcs[2] = {a, bh};
#pragma unroll
    for (int m = 0; m < 2; m++) {
#pragma unroll
        for (int q = 0; q < 2; q++) {
            int c = tid * 2 + q;          // 0..511
            int row = c >> 2;             // 0..127
            int kch = c & 3;              // 16B chunk within the 64B row
            uint32_t dst = st + m * MAT_BYTES + row * STRIDE_B + kch * 16;
            const unsigned short* src = srcs[m] + (size_t)row * K + kc * 32 + kch * 8;
            CP_ASYNC16(dst, src);
        }
    }
    asm volatile("cp.async.commit_group;" ::: "memory");
}

// ---------------------------------------------------------------------------
// Single-pass fp16 GEMM. CTA 128x128, warp 64x32, K-chunk 32, 4-stage, 2 CTAs/SM.
// MODE 0: C = A@Wh^T + bias. MODE 1: C (+)= gate * (A@Wh^T + bias).
// ---------------------------------------------------------------------------
template <int MODE>
__global__ __launch_bounds__(256, 2)
void tc_gemm_single(const unsigned short* __restrict__ Ag,
                    const unsigned short* __restrict__ Bhg,
                    const float* __restrict__ bias, float* __restrict__ C,
                    int N, int K, int expert, int isFirst) {
    extern __shared__ __align__(16) char dynsmem[];
    const uint32_t sbase = smem_to_u32(dynsmem);
    const int tid = threadIdx.x;
    const int wid = tid >> 5, lane = tid & 31;
    const int wm = wid & 1, wn = wid >> 1;
    const int KT = K >> 5;

    const unsigned short* a  = Ag  + (size_t)(blockIdx.y * 128) * K;
    const unsigned short* bh = Bhg + (size_t)(blockIdx.x * 128) * K;

    float acc[4][4][4];
#pragma unroll
    for (int i = 0; i < 4; i++)
#pragma unroll
        for (int j = 0; j < 4; j++)
#pragma unroll
            for (int q = 0; q < 4; q++) acc[i][j][q] = 0.f;

    copy_stage2(sbase + 0 * SGL_STAGE, tid, 0, K, a, bh);
    copy_stage2(sbase + 1 * SGL_STAGE, tid, 1, K, a, bh);
    copy_stage2(sbase + 2 * SGL_STAGE, tid, 2, K, a, bh);

    const uint32_t a_row = wm * 64 + (lane & 15);
    const uint32_t a_koff = (lane >> 4) * 16;
    const uint32_t b_row = wn * 32 + (lane >> 4) * 8 + (lane & 7);
    const uint32_t b_koff = ((lane >> 3) & 1) * 16;

    for (int kc = 0; kc < KT; kc++) {
        if (kc + 2 < KT)      asm volatile("cp.async.wait_group 2;" ::: "memory");
        else if (kc + 1 < KT) asm volatile("cp.async.wait_group 1;" ::: "memory");
        else                  asm volatile("cp.async.wait_group 0;" ::: "memory");
        __syncthreads();
        if (kc + 3 < KT)
            copy_stage2(sbase + ((kc + 3) & 3) * SGL_STAGE, tid, kc + 3, K, a, bh);

        const uint32_t st = sbase + (kc & 3) * SGL_STAGE;
#pragma unroll
        for (int h = 0; h < 2; h++) {
            const uint32_t kbyte = h * 32;
            uint32_t fa[16], fbh[8];
#pragma unroll
            for (int i = 0; i < 4; i++)
                ldsm_x4(&fa[i * 4], st + (a_row + i * 16) * STRIDE_B + kbyte + a_koff);
#pragma unroll
            for (int p = 0; p < 2; p++)
                ldsm_x4(&fbh[p * 4],
                        st + MAT_BYTES + (b_row + p * 16) * STRIDE_B + kbyte + b_koff);
#pragma unroll
            for (int i = 0; i < 4; i++)
#pragma unroll
                for (int j = 0; j < 4; j++)
                    mma_f16(acc[i][j], &fa[i * 4], &fbh[(j >> 1) * 4 + (j & 1) * 2]);
        }
    }

    const int r0 = blockIdx.y * 128 + wm * 64 + (lane >> 2);
    const int cbase = blockIdx.x * 128 + wn * 32 + (lane & 3) * 2;
#pragma unroll
    for (int i = 0; i < 4; i++) {
        const int rowA = r0 + i * 16;
        const int rowB = rowA + 8;
        float gA = 0.f, gB = 0.f;
        if (MODE == 1) {
            gA = g_gate[(size_t)rowA * E_ + expert];
            gB = g_gate[(size_t)rowB * E_ + expert];
        }
#pragma unroll
        for (int j = 0; j < 4; j++) {
            const int col = cbase + j * 8;
            float b0 = bias[col], b1 = bias[col + 1];
            float* pA = C + (size_t)rowA * N + col;
            float* pB = C + (size_t)rowB * N + col;
            if (MODE == 0) {
                *reinterpret_cast<float2*>(pA) =
                    make_float2(acc[i][j][0] + b0, acc[i][j][1] + b1);
                *reinterpret_cast<float2*>(pB) =
                    make_float2(acc[i][j][2] + b0, acc[i][j][3] + b1);
            } else {
                float2 oA = isFirst ? make_float2(0.f, 0.f)
                                    : *reinterpret_cast<const float2*>(pA);
                float2 oB = isFirst ? make_float2(0.f, 0.f)
                                    : *reinterpret_cast<const float2*>(pB);
                oA.x += gA * (acc[i][j][0] + b0);
                oA.y += gA * (acc[i][j][1] + b1);
                oB.x += gB * (acc[i][j][2] + b0);
                oB.y += gB * (acc[i][j][3] + b1);
                *reinterpret_cast<float2*>(pA) = oA;
                *reinterpret_cast<float2*>(pB) = oB;
            }
        }
    }
}

// ---------------------------------------------------------------------------
// Launch
// ---------------------------------------------------------------------------
extern "C" void kernel_launch(void* const* d_in, const int* in_sizes, int n_in,
                              void* d_out, int out_size) {
    const float* x  = (const float*)d_in[0];
    const float* Wg = (const float*)d_in[1];
    const float* bg = (const float*)d_in[2];
    const float* W1 = (const float*)d_in[3];
    const float* b1 = (const float*)d_in[4];
    const float* W2 = (const float*)d_in[5];
    const float* b2 = (const float*)d_in[6];
    const float* W3 = (const float*)d_in[7];
    const float* b3 = (const float*)d_in[8];
    const float* W4 = (const float*)d_in[9];
    const float* b4 = (const float*)d_in[10];
    const float* W5 = (const float*)d_in[11];
    const float* b5 = (const float*)d_in[12];
    float* out = (float*)d_out;

    void *pWh, *pX, *pA, *pC;
    cudaGetSymbolAddress(&pWh, g_Wh);
    cudaGetSymbolAddress(&pX, g_X);
    cudaGetSymbolAddress(&pA, g_A);
    cudaGetSymbolAddress(&pC, g_C);
    unsigned short* Wh = (unsigned short*)pWh;
    unsigned short* X = (unsigned short*)pX;
    unsigned short* A = (unsigned short*)pA;
    float* Cbuf = (float*)pC;

    cudaFuncSetAttribute(tc_gemm_single<0>, cudaFuncAttributeMaxDynamicSharedMemorySize, SGL_SMEM);
    cudaFuncSetAttribute(tc_gemm_single<1>, cudaFuncAttributeMaxDynamicSharedMemorySize, SGL_SMEM);

    const size_t off1 = 0;
    const size_t off2 = off1 + (size_t)DIN_ * H_;
    const size_t off3 = off2 + (size_t)H_ * H_;
    const size_t off4 = off3 + (size_t)H_ * H_;
    const size_t off5 = off4 + (size_t)H_ * H_;

    const dim3 wblk(32, 8);
    const dim3 gridH(H_ / 128, B_ / 128);
    const dim3 gridO(DOUT_ / 128, B_ / 128);

    // ncu -s 5 -c 1 profiles launch index 5 => tc_gemm_single<0> (L2, e0):
    // 0: wconv L1(e0), 1: wconv L2(e0), 2: xconv, 3: gemm1, 4: mish1, 5: gemm2.
    {
        wconv_hi<<<dim3(H_ / 32, DIN_ / 64), wblk>>>(W1, Wh + off1, DIN_, H_);
        wconv_hi<<<dim3(H_ / 32, H_ / 64), wblk>>>(W2, Wh + off2, H_, H_);
        xconv_kernel<<<(B_ * DIN_ / 4 + 255) / 256, 256>>>(x, X, B_ * DIN_ / 4);
        tc_gemm_single<0><<<gridH, 256, SGL_SMEM>>>(X, Wh + off1, b1, Cbuf, H_, DIN_, 0, 0);
        mish_ln_cvt_kernel<<<B_, 256>>>(Cbuf, A);
        tc_gemm_single<0><<<gridH, 256, SGL_SMEM>>>(A, Wh + off2, b2, Cbuf, H_, H_, 0, 0);
        gate_kernel<<<B_ / 8, 256>>>(x, Wg, bg);
        wconv_hi<<<dim3(H_ / 32, H_ / 64), wblk>>>(W3, Wh + off3, H_, H_);
        wconv_hi<<<dim3(H_ / 32, H_ / 64), wblk>>>(W4, Wh + off4, H_, H_);
        wconv_hi<<<dim3(DOUT_ / 32, H_ / 64), wblk>>>(W5, Wh + off5, H_, DOUT_);
        mish_ln_cvt_kernel<<<B_, 256>>>(Cbuf, A);
        tc_gemm_single<0><<<gridH, 256, SGL_SMEM>>>(A, Wh + off3, b3, Cbuf, H_, H_, 0, 0);
        mish_ln_cvt_kernel<<<B_, 256>>>(Cbuf, A);
        tc_gemm_single<0><<<gridH, 256, SGL_SMEM>>>(A, Wh + off4, b4, Cbuf, H_, H_, 0, 0);
        mish_ln_cvt_kernel<<<B_, 256>>>(Cbuf, A);
        tc_gemm_single<1><<<gridO, 256, SGL_SMEM>>>(A, Wh + off5, b5, out, DOUT_, H_, 0, 1);
    }

    for (int e = 1; e < E_; e++) {
        const size_t eb = (size_t)e * WPE;
        const float* W1e = W1 + (size_t)e * DIN_ * H_;
        const float* W2e = W2 + (size_t)e * H_ * H_;
        const float* W3e = W3 + (size_t)e * H_ * H_;
        const float* W4e = W4 + (size_t)e * H_ * H_;
        const float* W5e = W5 + (size_t)e * H_ * DOUT_;
        const float* b1e = b1 + (size_t)e * H_;
        const float* b2e = b2 + (size_t)e * H_;
        const float* b3e = b3 + (size_t)e * H_;
        const float* b4e = b4 + (size_t)e * H_;
        const float* b5e = b5 + (size_t)e * DOUT_;

        wconv_hi<<<dim3(H_ / 32, DIN_ / 64), wblk>>>(W1e, Wh + eb + off1, DIN_, H_);
        wconv_hi<<<dim3(H_ / 32, H_ / 64), wblk>>>(W2e, Wh + eb + off2, H_, H_);
        wconv_hi<<<dim3(H_ / 32, H_ / 64), wblk>>>(W3e, Wh + eb + off3, H_, H_);
        wconv_hi<<<dim3(H_ / 32, H_ / 64), wblk>>>(W4e, Wh + eb + off4, H_, H_);
        wconv_hi<<<dim3(DOUT_ / 32, H_ / 64), wblk>>>(W5e, Wh + eb + off5, H_, DOUT_);

        tc_gemm_single<0><<<gridH, 256, SGL_SMEM>>>(X, Wh + eb + off1, b1e, Cbuf, H_, DIN_, 0, 0);
        mish_ln_cvt_kernel<<<B_, 256>>>(Cbuf, A);
        tc_gemm_single<0><<<gridH, 256, SGL_SMEM>>>(A, Wh + eb + off2, b2e, Cbuf, H_, H_, 0, 0);
        mish_ln_cvt_kernel<<<B_, 256>>>(Cbuf, A);
        tc_gemm_single<0><<<gridH, 256, SGL_SMEM>>>(A, Wh + eb + off3, b3e, Cbuf, H_, H_, 0, 0);
        mish_ln_cvt_kernel<<<B_, 256>>>(Cbuf, A);
        tc_gemm_single<0><<<gridH, 256, SGL_SMEM>>>(A, Wh + eb + off4, b4e, Cbuf, H_, H_, 0, 0);
        mish_ln_cvt_kernel<<<B_, 256>>>(Cbuf, A);
        tc_gemm_single<1><<<gridO, 256, SGL_SMEM>>>(A, Wh + eb + off5, b5e, out, DOUT_, H_, e, 0);
    }
}

// round 9
// speedup vs baseline: 6.3862x; 1.1040x over previous
#include <cuda_runtime.h>
#include <cuda_fp16.h>
#include <math.h>
#include <stdint.h>

#define B_    8192
#define DIN_  1024
#define H_    2048
#define DOUT_ 1024
#define E_    8

// ---------------------------------------------------------------------------
// Scratch (allocation-free __device__ globals)
// ---------------------------------------------------------------------------
#define WPE 16777216ull  // weight elements per expert (5 layers, transposed [N,K])
#define ACT_STRIDE ((size_t)B_ * H_)    // per-expert activation stride (elems)
__device__ unsigned short g_Wh[WPE * E_];            // fp16 weights (all layers, all experts)
__device__ unsigned short g_X[(size_t)B_ * DIN_];    // fp16 input acts (shared)
__device__ unsigned short g_A[ACT_STRIDE * E_];      // fp16 per-expert activations
__device__ float g_C[ACT_STRIDE * E_];               // fp32 per-expert GEMM out / final Y
__device__ float g_gate[(size_t)B_ * E_];

// ---------------------------------------------------------------------------
// PTX helpers
// ---------------------------------------------------------------------------
__device__ __forceinline__ uint32_t smem_to_u32(const void* smem_ptr) {
    uint32_t addr;
    asm("{ .reg .u64 tmp; cvta.to.shared.u64 tmp, %1; cvt.u32.u64 %0, tmp; }"
        : "=r"(addr) : "l"(smem_ptr));
    return addr;
}

#define CP_ASYNC16(dst, src) \
    asm volatile("cp.async.cg.shared.global [%0], [%1], 16;" \
                 :: "r"((uint32_t)(dst)), "l"(src) : "memory")

__device__ __forceinline__ void ldsm_x4(uint32_t* r, uint32_t addr) {
    asm volatile("ldmatrix.sync.aligned.m8n8.x4.shared.b16 {%0,%1,%2,%3}, [%4];"
                 : "=r"(r[0]), "=r"(r[1]), "=r"(r[2]), "=r"(r[3]) : "r"(addr));
}

__device__ __forceinline__ void mma_f16(float* c, const uint32_t* a, const uint32_t* b) {
    asm volatile(
        "mma.sync.aligned.m16n8k16.row.col.f32.f16.f16.f32 "
        "{%0,%1,%2,%3}, {%4,%5,%6,%7}, {%8,%9}, {%0,%1,%2,%3};"
        : "+f"(c[0]), "+f"(c[1]), "+f"(c[2]), "+f"(c[3])
        : "r"(a[0]), "r"(a[1]), "r"(a[2]), "r"(a[3]), "r"(b[0]), "r"(b[1]));
}

// ---------------------------------------------------------------------------
// Gate: softmax(x @ Wg + bg) per row. One warp/row.
// ---------------------------------------------------------------------------
__global__ void gate_kernel(const float* __restrict__ x,
                            const float* __restrict__ Wg,
                            const float* __restrict__ bg) {
    int gwarp = (blockIdx.x * blockDim.x + threadIdx.x) >> 5;
    int lane  = threadIdx.x & 31;
    if (gwarp >= B_) return;
    const float* xr = x + (size_t)gwarp * DIN_;
    float acc[E_];
#pragma unroll
    for (int e = 0; e < E_; e++) acc[e] = 0.f;
    for (int i = lane; i < DIN_; i += 32) {
        float xv = xr[i];
        const float4* w4 = reinterpret_cast<const float4*>(Wg + (size_t)i * E_);
        float4 w0 = w4[0], w1 = w4[1];
        acc[0] += xv * w0.x; acc[1] += xv * w0.y;
        acc[2] += xv * w0.z; acc[3] += xv * w0.w;
        acc[4] += xv * w1.x; acc[5] += xv * w1.y;
        acc[6] += xv * w1.z; acc[7] += xv * w1.w;
    }
#pragma unroll
    for (int e = 0; e < E_; e++) {
#pragma unroll
        for (int o = 16; o > 0; o >>= 1)
            acc[e] += __shfl_xor_sync(0xffffffffu, acc[e], o);
    }
    if (lane == 0) {
        float mx = -1e30f;
#pragma unroll
        for (int e = 0; e < E_; e++) { acc[e] += bg[e]; mx = fmaxf(mx, acc[e]); }
        float s = 0.f;
#pragma unroll
        for (int e = 0; e < E_; e++) { acc[e] = expf(acc[e] - mx); s += acc[e]; }
        float inv = 1.f / s;
#pragma unroll
        for (int e = 0; e < E_; e++) g_gate[(size_t)gwarp * E_ + e] = acc[e] * inv;
    }
}

// ---------------------------------------------------------------------------
// Weight convert+transpose, batched over experts (blockIdx.z):
// W [E,K,N] fp32 -> [E][N,K] fp16 (per-expert stride WPE on output).
// ---------------------------------------------------------------------------
__global__ void wconv_hi(const float* __restrict__ Wbase,
                         unsigned short* __restrict__ Whbase,
                         int K, int N) {
    __shared__ float t[64][33];
    const float* W = Wbase + (size_t)blockIdx.z * K * N;
    unsigned short* Wh = Whbase + (size_t)blockIdx.z * WPE;
    const int n0 = blockIdx.x * 32, k0 = blockIdx.y * 64;
    const int tx = threadIdx.x, ty = threadIdx.y;  // 32x8
#pragma unroll
    for (int r = 0; r < 8; r++) {
        int k = ty + r * 8;
        t[k][tx] = W[(size_t)(k0 + k) * N + n0 + tx];
    }
    __syncthreads();
#pragma unroll
    for (int r = 0; r < 4; r++) {
        int n = ty + r * 8;
        __half h0 = __float2half_rn(t[2 * tx][n]);
        __half h1 = __float2half_rn(t[2 * tx + 1][n]);
        size_t o = (size_t)(n0 + n) * K + k0 + 2 * tx;
        *reinterpret_cast<ushort2*>(&Wh[o]) =
            make_ushort2(__half_as_ushort(h0), __half_as_ushort(h1));
    }
}

// ---------------------------------------------------------------------------
// x convert: fp32 -> fp16.
// ---------------------------------------------------------------------------
__global__ void xconv_kernel(const float* __restrict__ x,
                             unsigned short* __restrict__ X, int n4) {
    int i = blockIdx.x * blockDim.x + threadIdx.x;
    if (i >= n4) return;
    float4 v = reinterpret_cast<const float4*>(x)[i];
    ushort4 o;
    o.x = __half_as_ushort(__float2half_rn(v.x));
    o.y = __half_as_ushort(__float2half_rn(v.y));
    o.z = __half_as_ushort(__float2half_rn(v.z));
    o.w = __half_as_ushort(__float2half_rn(v.w));
    reinterpret_cast<ushort4*>(X)[i] = o;
}

// ---------------------------------------------------------------------------
// Fast mish: tanh(softplus(h)) = (u^2+2u)/(u^2+2u+2), u = e^h.
// ---------------------------------------------------------------------------
__device__ __forceinline__ float mish_fast(float h) {
    if (h > 20.f) return h;
    float u = __expf(h);
    float w = u * (u + 2.f);
    return h * __fdividef(w, w + 2.f);
}

// ---------------------------------------------------------------------------
// mish + LayerNorm + fp16 convert, batched over experts (blockIdx.y).
// Row of H_=2048, 256 threads.
// ---------------------------------------------------------------------------
__global__ void mish_ln_cvt_kernel(const float* __restrict__ Cbase,
                                   unsigned short* __restrict__ Abase) {
    __shared__ float sred[64];
    const int t = threadIdx.x;
    const size_t rowoff = ((size_t)blockIdx.y * B_ + blockIdx.x) * H_;
    const float4* p = reinterpret_cast<const float4*>(Cbase + rowoff);
    float4 v0 = p[t], v1 = p[t + 256];
    float vals[8] = {v0.x, v0.y, v0.z, v0.w, v1.x, v1.y, v1.z, v1.w};
    float s = 0.f, q = 0.f;
#pragma unroll
    for (int i = 0; i < 8; i++) {
        float m = mish_fast(vals[i]);
        vals[i] = m;
        s += m;
        q += m * m;
    }
#pragma unroll
    for (int o = 16; o > 0; o >>= 1) {
        s += __shfl_xor_sync(0xffffffffu, s, o);
        q += __shfl_xor_sync(0xffffffffu, q, o);
    }
    const int w = t >> 5;
    if ((t & 31) == 0) { sred[w] = s; sred[w + 32] = q; }
    __syncthreads();
    if (t < 32) {
        float rs = (t < 8) ? sred[t] : 0.f;
        float rq = (t < 8) ? sred[t + 32] : 0.f;
#pragma unroll
        for (int o = 4; o > 0; o >>= 1) {
            rs += __shfl_xor_sync(0xffffffffu, rs, o);
            rq += __shfl_xor_sync(0xffffffffu, rq, o);
        }
        if (t == 0) { sred[0] = rs; sred[32] = rq; }
    }
    __syncthreads();
    const float mu = sred[0] * (1.f / H_);
    const float var = sred[32] * (1.f / H_) - mu * mu;
    const float inv = rsqrtf(var + 1e-5f);
    unsigned short h8[8];
#pragma unroll
    for (int i = 0; i < 8; i++)
        h8[i] = __half_as_ushort(__float2half_rn((vals[i] - mu) * inv));
    ushort4* oa = reinterpret_cast<ushort4*>(Abase + rowoff);
    oa[t]       = make_ushort4(h8[0], h8[1], h8[2], h8[3]);
    oa[t + 256] = make_ushort4(h8[4], h8[5], h8[6], h8[7]);
}

// ---------------------------------------------------------------------------
// GEMM geometry
// ---------------------------------------------------------------------------
#define STRIDE_B 80                      // padded row stride in bytes
#define MAT_BYTES (128 * STRIDE_B)       // 10240
#define NSTAGE 4
#define SGL_STAGE (2 * MAT_BYTES)        // A, Wh
#define SGL_SMEM (NSTAGE * SGL_STAGE)    // 81920

__device__ __forceinline__ void copy_stage2(uint32_t st, int tid, int kc, int K,
                                            const unsigned short* a,
                                            const unsigned short* bh) {
    const unsigned short* srcs[2] = {a, bh};
#pragma unroll
    for (int m = 0; m < 2; m++) {
#pragma unroll
        for (int q = 0; q < 2; q++) {
            int c = tid * 2 + q;          // 0..511
            int row = c >> 2;             // 0..127
            int kch = c & 3;              // 16B chunk within the 64B row
            uint32_t dst = st + m * MAT_BYTES + row * STRIDE_B + kch * 16;
            const unsigned short* src = srcs[m] + (size_t)row * K + kc * 32 + kch * 8;
            CP_ASYNC16(dst, src);
        }
    }
    asm volatile("cp.async.commit_group;" ::: "memory");
}

// ---------------------------------------------------------------------------
// Single-pass fp16 GEMM, batched over experts (blockIdx.z).
// CTA 128x128, warp 64x32, K-chunk 32, 4-stage, 2 CTAs/SM.
// MODE 0: C[z] = A[z]@W[z]^T + bias[z]
// MODE 1: C[z] = gate[row,z] * (A[z]@W[z]^T + bias[z])   (no accumulation)
// strideA = 0 lets all experts share one input (L1 / X).
// ---------------------------------------------------------------------------
template <int MODE>
__global__ __launch_bounds__(256, 2)
void tc_gemm_single(const unsigned short* __restrict__ Ag,
                    const unsigned short* __restrict__ Wg,
                    const float* __restrict__ biasg, float* __restrict__ Cg,
                    int N, int K, size_t strideA) {
    extern __shared__ __align__(16) char dynsmem[];
    const uint32_t sbase = smem_to_u32(dynsmem);
    const int tid = threadIdx.x;
    const int wid = tid >> 5, lane = tid & 31;
    const int wm = wid & 1, wn = wid >> 1;
    const int KT = K >> 5;
    const int ez = blockIdx.z;

    const unsigned short* a  = Ag + (size_t)ez * strideA + (size_t)(blockIdx.y * 128) * K;
    const unsigned short* bh = Wg + (size_t)ez * WPE + (size_t)(blockIdx.x * 128) * K;
    const float* bias = biasg + (size_t)ez * N;
    float* C = Cg + (size_t)ez * ACT_STRIDE;

    float acc[4][4][4];
#pragma unroll
    for (int i = 0; i < 4; i++)
#pragma unroll
        for (int j = 0; j < 4; j++)
#pragma unroll
            for (int q = 0; q < 4; q++) acc[i][j][q] = 0.f;

    copy_stage2(sbase + 0 * SGL_STAGE, tid, 0, K, a, bh);
    copy_stage2(sbase + 1 * SGL_STAGE, tid, 1, K, a, bh);
    copy_stage2(sbase + 2 * SGL_STAGE, tid, 2, K, a, bh);

    const uint32_t a_row = wm * 64 + (lane & 15);
    const uint32_t a_koff = (lane >> 4) * 16;
    const uint32_t b_row = wn * 32 + (lane >> 4) * 8 + (lane & 7);
    const uint32_t b_koff = ((lane >> 3) & 1) * 16;

    for (int kc = 0; kc < KT; kc++) {
        if (kc + 2 < KT)      asm volatile("cp.async.wait_group 2;" ::: "memory");
        else if (kc + 1 < KT) asm volatile("cp.async.wait_group 1;" ::: "memory");
        else                  asm volatile("cp.async.wait_group 0;" ::: "memory");
        __syncthreads();
        if (kc + 3 < KT)
            copy_stage2(sbase + ((kc + 3) & 3) * SGL_STAGE, tid, kc + 3, K, a, bh);

        const uint32_t st = sbase + (kc & 3) * SGL_STAGE;
#pragma unroll
        for (int h = 0; h < 2; h++) {
            const uint32_t kbyte = h * 32;
            uint32_t fa[16], fbh[8];
#pragma unroll
            for (int i = 0; i < 4; i++)
                ldsm_x4(&fa[i * 4], st + (a_row + i * 16) * STRIDE_B + kbyte + a_koff);
#pragma unroll
            for (int p = 0; p < 2; p++)
                ldsm_x4(&fbh[p * 4],
                        st + MAT_BYTES + (b_row + p * 16) * STRIDE_B + kbyte + b_koff);
#pragma unroll
            for (int i = 0; i < 4; i++)
#pragma unroll
                for (int j = 0; j < 4; j++)
                    mma_f16(acc[i][j], &fa[i * 4], &fbh[(j >> 1) * 4 + (j & 1) * 2]);
        }
    }

    const int r0 = blockIdx.y * 128 + wm * 64 + (lane >> 2);
    const int cbase = blockIdx.x * 128 + wn * 32 + (lane & 3) * 2;
#pragma unroll
    for (int i = 0; i < 4; i++) {
        const int rowA = r0 + i * 16;
        const int rowB = rowA + 8;
        float gA = 1.f, gB = 1.f;
        if (MODE == 1) {
            gA = g_gate[(size_t)rowA * E_ + ez];
            gB = g_gate[(size_t)rowB * E_ + ez];
        }
#pragma unroll
        for (int j = 0; j < 4; j++) {
            const int col = cbase + j * 8;
            float b0 = bias[col], b1 = bias[col + 1];
            float* pA = C + (size_t)rowA * N + col;
            float* pB = C + (size_t)rowB * N + col;
            if (MODE == 0) {
                *reinterpret_cast<float2*>(pA) =
                    make_float2(acc[i][j][0] + b0, acc[i][j][1] + b1);
                *reinterpret_cast<float2*>(pB) =
                    make_float2(acc[i][j][2] + b0, acc[i][j][3] + b1);
            } else {
                *reinterpret_cast<float2*>(pA) =
                    make_float2(gA * (acc[i][j][0] + b0), gA * (acc[i][j][1] + b1));
                *reinterpret_cast<float2*>(pB) =
                    make_float2(gB * (acc[i][j][2] + b0), gB * (acc[i][j][3] + b1));
            }
        }
    }
}

// ---------------------------------------------------------------------------
// Combine: out = sum over experts of gated partials Y[e] (stored in g_C slots).
// ---------------------------------------------------------------------------
__global__ void combine_kernel(const float* __restrict__ Cbase,
                               float* __restrict__ out, int n4) {
    int i = blockIdx.x * blockDim.x + threadIdx.x;
    if (i >= n4) return;
    float4 s = make_float4(0.f, 0.f, 0.f, 0.f);
#pragma unroll
    for (int e = 0; e < E_; e++) {
        float4 v = *reinterpret_cast<const float4*>(Cbase + (size_t)e * ACT_STRIDE + i * 4);
        s.x += v.x; s.y += v.y; s.z += v.z; s.w += v.w;
    }
    reinterpret_cast<float4*>(out)[i] = s;
}

// ---------------------------------------------------------------------------
// Launch
// ---------------------------------------------------------------------------
extern "C" void kernel_launch(void* const* d_in, const int* in_sizes, int n_in,
                              void* d_out, int out_size) {
    const float* x  = (const float*)d_in[0];
    const float* Wg = (const float*)d_in[1];
    const float* bg = (const float*)d_in[2];
    const float* W1 = (const float*)d_in[3];
    const float* b1 = (const float*)d_in[4];
    const float* W2 = (const float*)d_in[5];
    const float* b2 = (const float*)d_in[6];
    const float* W3 = (const float*)d_in[7];
    const float* b3 = (const float*)d_in[8];
    const float* W4 = (const float*)d_in[9];
    const float* b4 = (const float*)d_in[10];
    const float* W5 = (const float*)d_in[11];
    const float* b5 = (const float*)d_in[12];
    float* out = (float*)d_out;

    void *pWh, *pX, *pA, *pC;
    cudaGetSymbolAddress(&pWh, g_Wh);
    cudaGetSymbolAddress(&pX, g_X);
    cudaGetSymbolAddress(&pA, g_A);
    cudaGetSymbolAddress(&pC, g_C);
    unsigned short* Wh = (unsigned short*)pWh;
    unsigned short* X = (unsigned short*)pX;
    unsigned short* A = (unsigned short*)pA;
    float* Cbuf = (float*)pC;

    cudaFuncSetAttribute(tc_gemm_single<0>, cudaFuncAttributeMaxDynamicSharedMemorySize, SGL_SMEM);
    cudaFuncSetAttribute(tc_gemm_single<1>, cudaFuncAttributeMaxDynamicSharedMemorySize, SGL_SMEM);

    // Per-expert layer offsets within g_Wh ([N,K] packed, stride WPE per expert)
    const size_t off1 = 0;
    const size_t off2 = off1 + (size_t)DIN_ * H_;
    const size_t off3 = off2 + (size_t)H_ * H_;
    const size_t off4 = off3 + (size_t)H_ * H_;
    const size_t off5 = off4 + (size_t)H_ * H_;

    const dim3 wblk(32, 8);
    const dim3 gridH(H_ / 128, B_ / 128, E_);
    const dim3 gridO(DOUT_ / 128, B_ / 128, E_);
    const dim3 gridM(B_, E_);

    // Launch order (ncu -s 5 -c 1 profiles index 5 = batched L1 GEMM):
    // 0 xconv, 1 wconv L1, 2 gate, 3 wconv L2, 4 wconv L3, 5 gemm L1,
    // 6 mish, 7 wconv L4, 8 wconv L5, 9 gemm L2, 10 mish, 11 gemm L3,
    // 12 mish, 13 gemm L4, 14 mish, 15 gemm L5, 16 combine.
    xconv_kernel<<<(B_ * DIN_ / 4 + 255) / 256, 256>>>(x, X, B_ * DIN_ / 4);
    wconv_hi<<<dim3(H_ / 32, DIN_ / 64, E_), wblk>>>(W1, Wh + off1, DIN_, H_);
    gate_kernel<<<B_ / 8, 256>>>(x, Wg, bg);
    wconv_hi<<<dim3(H_ / 32, H_ / 64, E_), wblk>>>(W2, Wh + off2, H_, H_);
    wconv_hi<<<dim3(H_ / 32, H_ / 64, E_), wblk>>>(W3, Wh + off3, H_, H_);

    tc_gemm_single<0><<<gridH, 256, SGL_SMEM>>>(X, Wh + off1, b1, Cbuf, H_, DIN_, 0);
    mish_ln_cvt_kernel<<<gridM, 256>>>(Cbuf, A);

    wconv_hi<<<dim3(H_ / 32, H_ / 64, E_), wblk>>>(W4, Wh + off4, H_, H_);
    wconv_hi<<<dim3(DOUT_ / 32, H_ / 64, E_), wblk>>>(W5, Wh + off5, H_, DOUT_);

    tc_gemm_single<0><<<gridH, 256, SGL_SMEM>>>(A, Wh + off2, b2, Cbuf, H_, H_, ACT_STRIDE);
    mish_ln_cvt_kernel<<<gridM, 256>>>(Cbuf, A);
    tc_gemm_single<0><<<gridH, 256, SGL_SMEM>>>(A, Wh + off3, b3, Cbuf, H_, H_, ACT_STRIDE);
    mish_ln_cvt_kernel<<<gridM, 256>>>(Cbuf, A);
    tc_gemm_single<0><<<gridH, 256, SGL_SMEM>>>(A, Wh + off4, b4, Cbuf, H_, H_, ACT_STRIDE);
    mish_ln_cvt_kernel<<<gridM, 256>>>(Cbuf, A);
    tc_gemm_single<1><<<gridO, 256, SGL_SMEM>>>(A, Wh + off5, b5, Cbuf, DOUT_, H_, ACT_STRIDE);

    combine_kernel<<<(B_ * DOUT_ / 4 + 255) / 256, 256>>>(Cbuf, out, B_ * DOUT_ / 4);
}